// round 1
// baseline (speedup 1.0000x reference)
#include <cuda_runtime.h>

#define BATCH 16
#define CIN   128
#define COUT  128
#define HH    64
#define WW    64
#define KK2   9
#define KC    (CIN*KK2)   // 1152

// Scratch (device globals: allocation-free rule)
__device__ float g_offmask[(size_t)BATCH*27*HH*WW];  // [b][27][h][w]; ch 0..17 offsets, 18..26 sigmoid(mask)
__device__ float g_wT[(size_t)KC*COUT];              // wT[k][o], k = c*9+n

typedef unsigned long long ull;

__device__ __forceinline__ ull pk2(float a, float b){
    ull r; asm("mov.b64 %0, {%1, %2};" : "=l"(r) : "f"(a), "f"(b)); return r;
}
__device__ __forceinline__ ull pk2s(float a){
    ull r; asm("mov.b64 %0, {%1, %1};" : "=l"(r) : "f"(a)); return r;
}
__device__ __forceinline__ ull f2fma(ull a, ull b, ull c){
    ull d; asm("fma.rn.f32x2 %0, %1, %2, %3;" : "=l"(d) : "l"(a), "l"(b), "l"(c)); return d;
}

// ---------------------------------------------------------------------------
// Kernel 0: transpose w_conv [o][c][n] -> wT[k=(c*9+n)][o]
// ---------------------------------------------------------------------------
__global__ void wtrans_kernel(const float* __restrict__ w_conv){
    int i = blockIdx.x * blockDim.x + threadIdx.x;
    if (i < KC*COUT){
        int o = i & 127;
        int k = i >> 7;
        g_wT[i] = w_conv[(size_t)o*KC + k];
    }
}

// ---------------------------------------------------------------------------
// Kernel 1: fused offset+mask conv (27 output channels, 3x3, pad 1)
// Block: 128 threads, covers 4 rows x 64 px of one image; thread = pixel pair.
// Grid: (16 htiles, 16 b)
// ---------------------------------------------------------------------------
__global__ __launch_bounds__(128) void offmask_kernel(
    const float* __restrict__ x,
    const float* __restrict__ w_off,  const float* __restrict__ b_off,
    const float* __restrict__ w_mask, const float* __restrict__ b_mask)
{
    __shared__ ull wsm[16*243];   // 16 channels x 27 oc x 9 taps, duplicated pairs

    const int b   = blockIdx.y;
    const int tid = threadIdx.x;
    const int r   = tid >> 5;           // 0..3
    const int pg  = tid & 31;           // 0..31
    const int h_  = blockIdx.x*4 + r;
    const int p0  = pg*2;

    ull acc[27];
    #pragma unroll
    for (int i = 0; i < 27; i++) acc[i] = 0ull;

    const float* xb = x + (size_t)b*CIN*HH*WW;

    for (int chunk = 0; chunk < 8; chunk++){
        __syncthreads();
        const int c0 = chunk*16;
        for (int i = tid; i < 16*243; i += 128){
            int cl = i/243, j = i - cl*243;
            int oc = j/9,  k = j - oc*9;
            int c  = c0 + cl;
            float wv = (oc < 18) ? w_off[((size_t)oc*CIN + c)*9 + k]
                                 : w_mask[((size_t)(oc-18)*CIN + c)*9 + k];
            wsm[i] = pk2s(wv);
        }
        __syncthreads();

        for (int cl = 0; cl < 16; cl++){
            const float* xc = xb + (size_t)(c0+cl)*HH*WW;
            ull xp[3][3];
            #pragma unroll
            for (int rr = 0; rr < 3; rr++){
                int y = h_ - 1 + rr;
                bool vy = ((unsigned)y < (unsigned)HH);
                const float* xr = xc + y*WW;
                float v0 = (vy && pg > 0 ) ? xr[p0-1] : 0.f;
                float v1 =  vy             ? xr[p0  ] : 0.f;
                float v2 =  vy             ? xr[p0+1] : 0.f;
                float v3 = (vy && pg < 31) ? xr[p0+2] : 0.f;
                xp[rr][0] = pk2(v0, v1);
                xp[rr][1] = pk2(v1, v2);
                xp[rr][2] = pk2(v2, v3);
            }
            const ull* wc = wsm + cl*243;
            #pragma unroll
            for (int oc = 0; oc < 27; oc++){
                #pragma unroll
                for (int rr = 0; rr < 3; rr++){
                    #pragma unroll
                    for (int kx = 0; kx < 3; kx++){
                        acc[oc] = f2fma(wc[oc*9 + rr*3 + kx], xp[rr][kx], acc[oc]);
                    }
                }
            }
        }
    }

    // epilogue: bias (+ sigmoid for mask channels), store
    #pragma unroll
    for (int oc = 0; oc < 27; oc++){
        union { ull u; float2 f; } cv; cv.u = acc[oc];
        float bias = (oc < 18) ? b_off[oc] : b_mask[oc-18];
        float a = cv.f.x + bias;
        float c = cv.f.y + bias;
        if (oc >= 18){
            a = 1.f/(1.f + __expf(-a));
            c = 1.f/(1.f + __expf(-c));
        }
        cv.f.x = a; cv.f.y = c;
        *reinterpret_cast<ull*>(&g_offmask[(((size_t)b*27 + oc)*HH + h_)*WW + p0]) = cv.u;
    }
}

// ---------------------------------------------------------------------------
// Kernel 2: deformable gather + 128x64 GEMM per (b,h) row.
// Block: 256 threads = 32 o-frags (4 o each) x 8 p-frags (8 px each).
// Grid: (64 h, 16 b)
// ---------------------------------------------------------------------------
__global__ __launch_bounds__(256) void deform_kernel(
    const float* __restrict__ x, float* __restrict__ out)
{
    __shared__ float s_samp[72*64];    // [k_local][p], k_local = cl*9+n (8 ch/chunk)
    __shared__ float s_wt[4][576];     // mask-folded bilinear weights per (n,p)
    __shared__ int   s_ai[4][576];     // clamped corner offsets within channel plane

    const int h_  = blockIdx.x;
    const int b   = blockIdx.y;
    const int tid = threadIdx.x;

    const float* xb = x + (size_t)b*CIN*HH*WW;
    const float* om = g_offmask + (size_t)b*27*HH*WW;

    // Precompute bilinear corner addresses + weights (mask & validity folded)
    for (int i = tid; i < 576; i += 256){
        int n = i >> 6, p = i & 63;
        float offy = om[((size_t)(2*n  )*HH + h_)*WW + p];
        float offx = om[((size_t)(2*n+1)*HH + h_)*WW + p];
        float m    = om[((size_t)(18+n )*HH + h_)*WW + p];
        float py = offy + (float)(h_ - 1 + n/3);
        float px = offx + (float)(p  - 1 + n%3);
        float fy = floorf(py), fx = floorf(px);
        int y0 = (int)fy, x0 = (int)fx;
        float ly = py - fy, lx = px - fx;
        float hy = 1.f - ly, hx = 1.f - lx;
        int y1 = y0 + 1, x1 = x0 + 1;
        float vy0 = ((unsigned)y0 < 64u) ? 1.f : 0.f;
        float vy1 = ((unsigned)y1 < 64u) ? 1.f : 0.f;
        float vx0 = ((unsigned)x0 < 64u) ? 1.f : 0.f;
        float vx1 = ((unsigned)x1 < 64u) ? 1.f : 0.f;
        int y0c = min(max(y0,0),63), y1c = min(max(y1,0),63);
        int x0c = min(max(x0,0),63), x1c = min(max(x1,0),63);
        s_wt[0][i] = m*hy*hx*vy0*vx0;
        s_wt[1][i] = m*hy*lx*vy0*vx1;
        s_wt[2][i] = m*ly*hx*vy1*vx0;
        s_wt[3][i] = m*ly*lx*vy1*vx1;
        s_ai[0][i] = y0c*WW + x0c;
        s_ai[1][i] = y0c*WW + x1c;
        s_ai[2][i] = y1c*WW + x0c;
        s_ai[3][i] = y1c*WW + x1c;
    }

    const int o_t = tid & 31;     // o-frag: channels o_t*4 .. o_t*4+3
    const int p_t = tid >> 5;     // p-frag: pixels p_t*8 .. p_t*8+7
    const int p8  = p_t*8;

    ull acc[4][4];
    #pragma unroll
    for (int a = 0; a < 4; a++)
        #pragma unroll
        for (int c = 0; c < 4; c++) acc[a][c] = 0ull;

    for (int chunk = 0; chunk < 16; chunk++){
        __syncthreads();
        const int c0 = chunk*8;

        // ---- gather: bilinear samples for 8 channels x 9 taps x 64 px ----
        for (int i = tid; i < 576; i += 256){
            float w00 = s_wt[0][i], w01 = s_wt[1][i];
            float w10 = s_wt[2][i], w11 = s_wt[3][i];
            int a00 = s_ai[0][i], a01 = s_ai[1][i];
            int a10 = s_ai[2][i], a11 = s_ai[3][i];
            const float* xp = xb + (size_t)c0*HH*WW;
            #pragma unroll
            for (int cl = 0; cl < 8; cl++){
                s_samp[cl*576 + i] =
                    w00*xp[a00] + w01*xp[a01] + w10*xp[a10] + w11*xp[a11];
                xp += HH*WW;
            }
        }
        __syncthreads();

        // ---- GEMM: acc[o4][p8] += wT[k][o] * samp[k][p], k = chunk*72..+71 ----
        const float4* wr = reinterpret_cast<const float4*>(g_wT) + (size_t)(chunk*72)*32 + o_t;
        #pragma unroll 6
        for (int kl = 0; kl < 72; kl++){
            float4 wv = __ldg(wr + (size_t)kl*32);
            ull w0 = pk2s(wv.x), w1 = pk2s(wv.y), w2 = pk2s(wv.z), w3 = pk2s(wv.w);
            const float* sr = s_samp + kl*64 + p8;
            ull s0 = *reinterpret_cast<const ull*>(sr + 0);
            ull s1 = *reinterpret_cast<const ull*>(sr + 2);
            ull s2 = *reinterpret_cast<const ull*>(sr + 4);
            ull s3 = *reinterpret_cast<const ull*>(sr + 6);
            acc[0][0] = f2fma(w0, s0, acc[0][0]);
            acc[0][1] = f2fma(w0, s1, acc[0][1]);
            acc[0][2] = f2fma(w0, s2, acc[0][2]);
            acc[0][3] = f2fma(w0, s3, acc[0][3]);
            acc[1][0] = f2fma(w1, s0, acc[1][0]);
            acc[1][1] = f2fma(w1, s1, acc[1][1]);
            acc[1][2] = f2fma(w1, s2, acc[1][2]);
            acc[1][3] = f2fma(w1, s3, acc[1][3]);
            acc[2][0] = f2fma(w2, s0, acc[2][0]);
            acc[2][1] = f2fma(w2, s1, acc[2][1]);
            acc[2][2] = f2fma(w2, s2, acc[2][2]);
            acc[2][3] = f2fma(w2, s3, acc[2][3]);
            acc[3][0] = f2fma(w3, s0, acc[3][0]);
            acc[3][1] = f2fma(w3, s1, acc[3][1]);
            acc[3][2] = f2fma(w3, s2, acc[3][2]);
            acc[3][3] = f2fma(w3, s3, acc[3][3]);
        }
    }

    // ---- epilogue: contiguous 32B per (thread, o) -> full sectors ----
    const int o4 = o_t*4;
    #pragma unroll
    for (int oj = 0; oj < 4; oj++){
        float* op = out + (((size_t)b*COUT + o4 + oj)*HH + h_)*WW + p8;
        ull* op8 = reinterpret_cast<ull*>(op);
        op8[0] = acc[oj][0];
        op8[1] = acc[oj][1];
        op8[2] = acc[oj][2];
        op8[3] = acc[oj][3];
    }
}

// ---------------------------------------------------------------------------
extern "C" void kernel_launch(void* const* d_in, const int* in_sizes, int n_in,
                              void* d_out, int out_size)
{
    const float* x      = (const float*)d_in[0];
    const float* w_conv = (const float*)d_in[1];
    const float* w_off  = (const float*)d_in[2];
    const float* b_off  = (const float*)d_in[3];
    const float* w_mask = (const float*)d_in[4];
    const float* b_mask = (const float*)d_in[5];
    float* out = (float*)d_out;

    wtrans_kernel<<<(KC*COUT + 511)/512, 512>>>(w_conv);
    offmask_kernel<<<dim3(16, 16), 128>>>(x, w_off, b_off, w_mask, b_mask);
    deform_kernel<<<dim3(64, 16), 256>>>(x, out);
}

// round 4
// speedup vs baseline: 1.3504x; 1.3504x over previous
#include <cuda_runtime.h>
#include <cuda_bf16.h>
#include <cstdint>

#define BATCH 16
#define CIN   128
#define COUT  128
#define HH    64
#define WW    64

// ---------------------------------------------------------------------------
// Scratch (device globals: allocation-free rule)
// ---------------------------------------------------------------------------
__device__ float g_offmask[(size_t)BATCH*27*HH*WW]; // [b][27][h][w]; 0..17 offsets, 18..26 sigmoid(mask)
// Weights pre-split to bf16 hi/lo, layout [stage s = n*2+half][o:128][k:64]
__device__ __nv_bfloat16 g_wAhi[18*128*64];
__device__ __nv_bfloat16 g_wAlo[18*128*64];

typedef unsigned long long ull;

// ---------------------------------------------------------------------------
// Helpers
// ---------------------------------------------------------------------------
__device__ __forceinline__ uint32_t smem_u32(const void* p){
    uint32_t a;
    asm("{ .reg .u64 t; cvta.to.shared.u64 t, %1; cvt.u32.u64 %0, t; }" : "=r"(a) : "l"(p));
    return a;
}

#define LDMX4(r, addr) \
    asm volatile("ldmatrix.sync.aligned.m8n8.x4.shared.b16 {%0,%1,%2,%3}, [%4];" \
        : "=r"((r)[0]), "=r"((r)[1]), "=r"((r)[2]), "=r"((r)[3]) : "r"(addr))

#define MMA16816(d, a, b) \
    asm volatile("mma.sync.aligned.m16n8k16.row.col.f32.bf16.bf16.f32 " \
        "{%0,%1,%2,%3}, {%4,%5,%6,%7}, {%8,%9}, {%0,%1,%2,%3};" \
        : "+f"((d)[0]), "+f"((d)[1]), "+f"((d)[2]), "+f"((d)[3]) \
        : "r"((a)[0]), "r"((a)[1]), "r"((a)[2]), "r"((a)[3]), \
          "r"((b)[0]), "r"((b)[1]))

#define CP_ASYNC16(dst, src) \
    asm volatile("cp.async.ca.shared.global [%0], [%1], 16;" :: "r"(dst), "l"(src))
#define CP_COMMIT()  asm volatile("cp.async.commit_group;" ::: "memory")
#define CP_WAIT0()   asm volatile("cp.async.wait_group 0;" ::: "memory")

__device__ __forceinline__ uint32_t pack_bf2(float v0, float v1){
    __nv_bfloat16 h0 = __float2bfloat16_rn(v0);
    __nv_bfloat16 h1 = __float2bfloat16_rn(v1);
    return ((uint32_t)__bfloat16_as_ushort(h1) << 16) | __bfloat16_as_ushort(h0);
}

// FFMA2 helpers for offmask kernel
__device__ __forceinline__ ull pk2(float a, float b){
    ull r; asm("mov.b64 %0, {%1, %2};" : "=l"(r) : "f"(a), "f"(b)); return r;
}
__device__ __forceinline__ ull pk2s(float a){
    ull r; asm("mov.b64 %0, {%1, %1};" : "=l"(r) : "f"(a)); return r;
}
__device__ __forceinline__ ull f2fma(ull a, ull b, ull c){
    ull d; asm("fma.rn.f32x2 %0, %1, %2, %3;" : "=l"(d) : "l"(a), "l"(b), "l"(c)); return d;
}

// ---------------------------------------------------------------------------
// Kernel 0: split w_conv [o][c][n] into bf16 hi/lo, layout [s=n*2+c/64][o][c%64]
// ---------------------------------------------------------------------------
__global__ void prep_w_kernel(const float* __restrict__ w_conv){
    int i = blockIdx.x * blockDim.x + threadIdx.x;
    if (i < 9*128*128){
        int n = i / (128*128);
        int o = (i >> 7) & 127;
        int c = i & 127;
        float w = w_conv[((size_t)o*128 + c)*9 + n];
        __nv_bfloat16 hi = __float2bfloat16_rn(w);
        float lo = w - __bfloat162float(hi);
        int s = n*2 + (c >> 6);
        size_t di = ((size_t)s*128 + o)*64 + (c & 63);
        g_wAhi[di] = hi;
        g_wAlo[di] = __float2bfloat16_rn(lo);
    }
}

// ---------------------------------------------------------------------------
// Kernel 1: fused offset+mask conv (27 out ch, 3x3, pad 1) — FFMA2 path
// ---------------------------------------------------------------------------
__global__ __launch_bounds__(128) void offmask_kernel(
    const float* __restrict__ x,
    const float* __restrict__ w_off,  const float* __restrict__ b_off,
    const float* __restrict__ w_mask, const float* __restrict__ b_mask)
{
    __shared__ ull wsm[16*243];

    const int b   = blockIdx.y;
    const int tid = threadIdx.x;
    const int r   = tid >> 5;
    const int pg  = tid & 31;
    const int h_  = blockIdx.x*4 + r;
    const int p0  = pg*2;

    ull acc[27];
    #pragma unroll
    for (int i = 0; i < 27; i++) acc[i] = 0ull;

    const float* xb = x + (size_t)b*CIN*HH*WW;

    for (int chunk = 0; chunk < 8; chunk++){
        __syncthreads();
        const int c0 = chunk*16;
        for (int i = tid; i < 16*243; i += 128){
            int cl = i/243, j = i - cl*243;
            int oc = j/9,  k = j - oc*9;
            int c  = c0 + cl;
            float wv = (oc < 18) ? w_off[((size_t)oc*CIN + c)*9 + k]
                                 : w_mask[((size_t)(oc-18)*CIN + c)*9 + k];
            wsm[i] = pk2s(wv);
        }
        __syncthreads();

        for (int cl = 0; cl < 16; cl++){
            const float* xc = xb + (size_t)(c0+cl)*HH*WW;
            ull xp[3][3];
            #pragma unroll
            for (int rr = 0; rr < 3; rr++){
                int y = h_ - 1 + rr;
                bool vy = ((unsigned)y < (unsigned)HH);
                const float* xr = xc + y*WW;
                float v0 = (vy && pg > 0 ) ? xr[p0-1] : 0.f;
                float v1 =  vy             ? xr[p0  ] : 0.f;
                float v2 =  vy             ? xr[p0+1] : 0.f;
                float v3 = (vy && pg < 31) ? xr[p0+2] : 0.f;
                xp[rr][0] = pk2(v0, v1);
                xp[rr][1] = pk2(v1, v2);
                xp[rr][2] = pk2(v2, v3);
            }
            const ull* wc = wsm + cl*243;
            #pragma unroll
            for (int oc = 0; oc < 27; oc++){
                #pragma unroll
                for (int rr = 0; rr < 3; rr++){
                    #pragma unroll
                    for (int kx = 0; kx < 3; kx++){
                        acc[oc] = f2fma(wc[oc*9 + rr*3 + kx], xp[rr][kx], acc[oc]);
                    }
                }
            }
        }
    }

    #pragma unroll
    for (int oc = 0; oc < 27; oc++){
        union { ull u; float2 f; } cv; cv.u = acc[oc];
        float bias = (oc < 18) ? b_off[oc] : b_mask[oc-18];
        float a = cv.f.x + bias;
        float c = cv.f.y + bias;
        if (oc >= 18){
            a = 1.f/(1.f + __expf(-a));
            c = 1.f/(1.f + __expf(-c));
        }
        cv.f.x = a; cv.f.y = c;
        *reinterpret_cast<ull*>(&g_offmask[(((size_t)b*27 + oc)*HH + h_)*WW + p0]) = cv.u;
    }
}

// ---------------------------------------------------------------------------
// Kernel 2: deform gather + mma.sync bf16 (3-pass hi/lo split)
// Block = (b, 2 h-rows): D[128 o][128 px], K=1152 in 18 stages of 64.
// smem: s_wt(18432) | s_ai(18432) | 2 stages x { Ahi 16K | Alo 16K | Bhi 16K | Blo 16K }
// ---------------------------------------------------------------------------
#define OFF_WT   0
#define OFF_AI   18432
#define OFF_STG  36864
#define STG_SZ   65536
#define DSM_BYTES (OFF_STG + 2*STG_SZ)

__device__ __forceinline__ void gather_stage(
    char* bufB_hi, const float* xb,
    const float* s_wt, const int* s_ai, int n_tap, int half, int tid)
{
    const int p  = tid & 127;
    const int cg = tid >> 7;            // 0/1 → 32-channel half of the 64
    const int ci = n_tap*128 + p;
    const float w00 = s_wt[ci],      w01 = s_wt[1152+ci];
    const float w10 = s_wt[2304+ci], w11 = s_wt[3456+ci];
    const int a00 = s_ai[ci],      a01 = s_ai[1152+ci];
    const int a10 = s_ai[2304+ci], a11 = s_ai[3456+ci];
    const float* xp = xb + (size_t)(half*64 + cg*32)*(HH*WW);
    const int prow = p*128;
    const int psw  = p & 7;

    #pragma unroll
    for (int g = 0; g < 4; g++){        // 8 channels -> one 16B chunk
        uint32_t hi[4], lo[4];
        #pragma unroll
        for (int e = 0; e < 4; e++){
            const float* xc0 = xp + (size_t)(g*8 + e*2)*(HH*WW);
            const float* xc1 = xc0 + HH*WW;
            float v0 = w00*xc0[a00] + w01*xc0[a01] + w10*xc0[a10] + w11*xc0[a11];
            float v1 = w00*xc1[a00] + w01*xc1[a01] + w10*xc1[a10] + w11*xc1[a11];
            __nv_bfloat16 h0 = __float2bfloat16_rn(v0);
            __nv_bfloat16 h1 = __float2bfloat16_rn(v1);
            float r0 = v0 - __bfloat162float(h0);
            float r1 = v1 - __bfloat162float(h1);
            hi[e] = ((uint32_t)__bfloat16_as_ushort(h1) << 16) | __bfloat16_as_ushort(h0);
            lo[e] = pack_bf2(r0, r1);
        }
        int chunk = cg*4 + g;
        uint32_t off = prow + (uint32_t)((chunk ^ psw) << 4);
        *(uint4*)(bufB_hi + off)         = make_uint4(hi[0], hi[1], hi[2], hi[3]);
        *(uint4*)(bufB_hi + 16384 + off) = make_uint4(lo[0], lo[1], lo[2], lo[3]);
    }
}

__device__ __forceinline__ void cpasync_A(uint32_t bufA_u32, int stage_s, int tid)
{
    const __nv_bfloat16* srcHi = g_wAhi + (size_t)stage_s*128*64;
    const __nv_bfloat16* srcLo = g_wAlo + (size_t)stage_s*128*64;
    #pragma unroll
    for (int r = 0; r < 4; r++){
        int id = r*256 + tid;           // 0..1023
        int o = id >> 3, q = id & 7;
        uint32_t dst = bufA_u32 + (uint32_t)(o*128 + ((q ^ (o & 7)) << 4));
        CP_ASYNC16(dst,         srcHi + (size_t)o*64 + q*8);
        CP_ASYNC16(dst + 16384, srcLo + (size_t)o*64 + q*8);
    }
}

__device__ __forceinline__ void mma_stage(
    uint32_t sA, uint32_t sB, float acc[2][8][4], int wm, int wn, int lane)
{
    const int ar  = (lane & 7) + (((lane >> 3) & 1) << 3);  // m within 16
    const int akh = (lane >> 4) & 1;
    const int o0  = wm*32 + ar;
    const int o1  = o0 + 16;
    const int br  = (lane & 7) + (((lane >> 4) & 1) << 3);  // n within 16
    const int bkh = (lane >> 3) & 1;

    #pragma unroll
    for (int ks = 0; ks < 4; ks++){
        uint32_t ahi0[4], ahi1[4], alo0[4], alo1[4];
        {
            int ca = ks*2 + akh;
            uint32_t off0 = (uint32_t)(o0*128 + ((ca ^ (o0 & 7)) << 4));
            uint32_t off1 = (uint32_t)(o1*128 + ((ca ^ (o1 & 7)) << 4));
            LDMX4(ahi0, sA + off0);
            LDMX4(ahi1, sA + off1);
            LDMX4(alo0, sA + 16384 + off0);
            LDMX4(alo1, sA + 16384 + off1);
        }
        uint32_t bhi[8][2], blo[8][2];
        {
            int cb = ks*2 + bkh;
            #pragma unroll
            for (int g = 0; g < 4; g++){
                int pr = wn*64 + g*16 + br;
                uint32_t off = (uint32_t)(pr*128 + ((cb ^ (pr & 7)) << 4));
                uint32_t t[4];
                LDMX4(t, sB + off);
                bhi[g*2][0] = t[0]; bhi[g*2][1] = t[1];
                bhi[g*2+1][0] = t[2]; bhi[g*2+1][1] = t[3];
                LDMX4(t, sB + 16384 + off);
                blo[g*2][0] = t[0]; blo[g*2][1] = t[1];
                blo[g*2+1][0] = t[2]; blo[g*2+1][1] = t[3];
            }
        }
        #pragma unroll
        for (int nf = 0; nf < 8; nf++){
            MMA16816(acc[0][nf], ahi0, bhi[nf]);
            MMA16816(acc[1][nf], ahi1, bhi[nf]);
            MMA16816(acc[0][nf], alo0, bhi[nf]);
            MMA16816(acc[1][nf], alo1, bhi[nf]);
            MMA16816(acc[0][nf], ahi0, blo[nf]);
            MMA16816(acc[1][nf], ahi1, blo[nf]);
        }
    }
}

__global__ __launch_bounds__(256) void deform_kernel(
    const float* __restrict__ x, float* __restrict__ out)
{
    extern __shared__ char dsm[];
    float* s_wt = (float*)(dsm + OFF_WT);
    int*   s_ai = (int*)  (dsm + OFF_AI);
    const uint32_t u_base = smem_u32(dsm);
    const uint32_t u_stg  = u_base + OFF_STG;

    const int tid  = threadIdx.x;
    const int wid  = tid >> 5;
    const int lane = tid & 31;
    const int wm   = wid & 3;
    const int wn   = wid >> 2;
    const int h0   = blockIdx.x * 2;
    const int b    = blockIdx.y;

    // ---- corner tables for all (tap n, px) ----
    const float* om = g_offmask + (size_t)b*27*HH*WW;
    for (int i = tid; i < 1152; i += 256){
        int n = i >> 7, rr = i & 127;
        int hh = rr >> 6, p = rr & 63;
        int h_ = h0 + hh;
        float offy = om[((size_t)(2*n  )*HH + h_)*WW + p];
        float offx = om[((size_t)(2*n+1)*HH + h_)*WW + p];
        float m    = om[((size_t)(18+n )*HH + h_)*WW + p];
        float py = offy + (float)(h_ - 1 + n/3);
        float px = offx + (float)(p  - 1 + n%3);
        float fy = floorf(py), fx = floorf(px);
        int y0 = (int)fy, x0 = (int)fx;
        float ly = py - fy, lx = px - fx;
        float hy = 1.f - ly, hx = 1.f - lx;
        int y1 = y0 + 1, x1 = x0 + 1;
        float vy0 = ((unsigned)y0 < 64u) ? 1.f : 0.f;
        float vy1 = ((unsigned)y1 < 64u) ? 1.f : 0.f;
        float vx0 = ((unsigned)x0 < 64u) ? 1.f : 0.f;
        float vx1 = ((unsigned)x1 < 64u) ? 1.f : 0.f;
        int y0c = min(max(y0,0),63), y1c = min(max(y1,0),63);
        int x0c = min(max(x0,0),63), x1c = min(max(x1,0),63);
        s_wt[0*1152 + i] = m*hy*hx*vy0*vx0;
        s_wt[1*1152 + i] = m*hy*lx*vy0*vx1;
        s_wt[2*1152 + i] = m*ly*hx*vy1*vx0;
        s_wt[3*1152 + i] = m*ly*lx*vy1*vx1;
        s_ai[0*1152 + i] = y0c*WW + x0c;
        s_ai[1*1152 + i] = y0c*WW + x1c;
        s_ai[2*1152 + i] = y1c*WW + x0c;
        s_ai[3*1152 + i] = y1c*WW + x1c;
    }
    __syncthreads();

    const float* xb = x + (size_t)b*CIN*HH*WW;

    float acc[2][8][4];
    #pragma unroll
    for (int a = 0; a < 2; a++)
        #pragma unroll
        for (int f = 0; f < 8; f++)
            #pragma unroll
            for (int e = 0; e < 4; e++) acc[a][f][e] = 0.f;

    // ---- prologue: stage 0 ----
    cpasync_A(u_stg, 0, tid);
    CP_COMMIT();
    gather_stage(dsm + OFF_STG + 32768, xb, s_wt, s_ai, 0, 0, tid);
    CP_WAIT0();
    __syncthreads();

    // ---- main loop over 18 K-stages (tap n = s>>1, half = s&1) ----
    for (int s = 0; s < 18; s++){
        const int cur = s & 1;
        const uint32_t uc = u_stg + (uint32_t)cur*STG_SZ;
        const int nxt = cur ^ 1;

        if (s < 17){
            cpasync_A(u_stg + (uint32_t)nxt*STG_SZ, s+1, tid);
            CP_COMMIT();
        }
        // stagger warps: half mma-first, half gather-first (pipe overlap)
        if (wid & 1){
            mma_stage(uc, uc + 32768, acc, wm, wn, lane);
            if (s < 17)
                gather_stage(dsm + OFF_STG + nxt*STG_SZ + 32768, xb, s_wt, s_ai,
                             (s+1) >> 1, (s+1) & 1, tid);
        } else {
            if (s < 17)
                gather_stage(dsm + OFF_STG + nxt*STG_SZ + 32768, xb, s_wt, s_ai,
                             (s+1) >> 1, (s+1) & 1, tid);
            mma_stage(uc, uc + 32768, acc, wm, wn, lane);
        }
        CP_WAIT0();
        __syncthreads();
    }

    // ---- epilogue: D[o][px] -> out[b][o][h0+wn][w] ----
    const int h_ = h0 + wn;
    #pragma unroll
    for (int mf = 0; mf < 2; mf++){
        int o = wm*32 + mf*16 + (lane >> 2);
        float* p0 = out + (((size_t)b*COUT + o    )*HH + h_)*WW;
        float* p1 = out + (((size_t)b*COUT + o + 8)*HH + h_)*WW;
        #pragma unroll
        for (int nf = 0; nf < 8; nf++){
            int w = nf*8 + 2*(lane & 3);
            *(float2*)(p0 + w) = make_float2(acc[mf][nf][0], acc[mf][nf][1]);
            *(float2*)(p1 + w) = make_float2(acc[mf][nf][2], acc[mf][nf][3]);
        }
    }
}

// ---------------------------------------------------------------------------
extern "C" void kernel_launch(void* const* d_in, const int* in_sizes, int n_in,
                              void* d_out, int out_size)
{
    const float* x      = (const float*)d_in[0];
    const float* w_conv = (const float*)d_in[1];
    const float* w_off  = (const float*)d_in[2];
    const float* b_off  = (const float*)d_in[3];
    const float* w_mask = (const float*)d_in[4];
    const float* b_mask = (const float*)d_in[5];
    float* out = (float*)d_out;

    cudaFuncSetAttribute(deform_kernel,
                         cudaFuncAttributeMaxDynamicSharedMemorySize, DSM_BYTES);

    prep_w_kernel<<<(9*128*128 + 255)/256, 256>>>(w_conv);
    offmask_kernel<<<dim3(16, 16), 128>>>(x, w_off, b_off, w_mask, b_mask);
    deform_kernel<<<dim3(32, 16), 256, DSM_BYTES>>>(x, out);
}

// round 5
// speedup vs baseline: 1.6256x; 1.2038x over previous
#include <cuda_runtime.h>
#include <cuda_bf16.h>
#include <cstdint>

#define BATCH 16
#define CIN   128
#define COUT  128
#define HH    64
#define WW    64

// ---------------------------------------------------------------------------
// Scratch (device globals: allocation-free rule)
// ---------------------------------------------------------------------------
__device__ float g_offmask[(size_t)BATCH*27*HH*WW]; // [b][27][h][w]; 0..17 offsets, 18..26 sigmoid(mask)
// Weights pre-split to bf16 hi/lo, layout [stage s = n*2+half][o:128][k:64]
__device__ __nv_bfloat16 g_wAhi[18*128*64];
__device__ __nv_bfloat16 g_wAlo[18*128*64];

typedef unsigned long long ull;

// ---------------------------------------------------------------------------
// Helpers
// ---------------------------------------------------------------------------
__device__ __forceinline__ uint32_t smem_u32(const void* p){
    uint32_t a;
    asm("{ .reg .u64 t; cvta.to.shared.u64 t, %1; cvt.u32.u64 %0, t; }" : "=r"(a) : "l"(p));
    return a;
}

#define LDMX4(r, addr) \
    asm volatile("ldmatrix.sync.aligned.m8n8.x4.shared.b16 {%0,%1,%2,%3}, [%4];" \
        : "=r"((r)[0]), "=r"((r)[1]), "=r"((r)[2]), "=r"((r)[3]) : "r"(addr))

#define MMA16816(d, a0, a1, a2, a3, b0, b1) \
    asm volatile("mma.sync.aligned.m16n8k16.row.col.f32.bf16.bf16.f32 " \
        "{%0,%1,%2,%3}, {%4,%5,%6,%7}, {%8,%9}, {%0,%1,%2,%3};" \
        : "+f"((d)[0]), "+f"((d)[1]), "+f"((d)[2]), "+f"((d)[3]) \
        : "r"(a0), "r"(a1), "r"(a2), "r"(a3), "r"(b0), "r"(b1))

#define CP_ASYNC16(dst, src) \
    asm volatile("cp.async.ca.shared.global [%0], [%1], 16;" :: "r"(dst), "l"(src))
#define CP_COMMIT()  asm volatile("cp.async.commit_group;" ::: "memory")
#define CP_WAIT0()   asm volatile("cp.async.wait_group 0;" ::: "memory")

// Named-barrier producer/consumer sync (512 threads total per pair)
#define BAR_SYNC(id)   asm volatile("bar.sync %0, 512;"   :: "r"(id) : "memory")
#define BAR_ARRIVE(id) asm volatile("bar.arrive %0, 512;" :: "r"(id) : "memory")

__device__ __forceinline__ uint32_t pack_bf2(float v0, float v1){
    __nv_bfloat16 h0 = __float2bfloat16_rn(v0);
    __nv_bfloat16 h1 = __float2bfloat16_rn(v1);
    return ((uint32_t)__bfloat16_as_ushort(h1) << 16) | __bfloat16_as_ushort(h0);
}

// FFMA2 helpers for offmask kernel
__device__ __forceinline__ ull pk2(float a, float b){
    ull r; asm("mov.b64 %0, {%1, %2};" : "=l"(r) : "f"(a), "f"(b)); return r;
}
__device__ __forceinline__ ull pk2s(float a){
    ull r; asm("mov.b64 %0, {%1, %1};" : "=l"(r) : "f"(a)); return r;
}
__device__ __forceinline__ ull f2fma(ull a, ull b, ull c){
    ull d; asm("fma.rn.f32x2 %0, %1, %2, %3;" : "=l"(d) : "l"(a), "l"(b), "l"(c)); return d;
}

// ---------------------------------------------------------------------------
// Kernel 0: split w_conv [o][c][n] into bf16 hi/lo, layout [s=n*2+c/64][o][c%64]
// ---------------------------------------------------------------------------
__global__ void prep_w_kernel(const float* __restrict__ w_conv){
    int i = blockIdx.x * blockDim.x + threadIdx.x;
    if (i < 9*128*128){
        int n = i / (128*128);
        int o = (i >> 7) & 127;
        int c = i & 127;
        float w = w_conv[((size_t)o*128 + c)*9 + n];
        __nv_bfloat16 hi = __float2bfloat16_rn(w);
        float lo = w - __bfloat162float(hi);
        int s = n*2 + (c >> 6);
        size_t di = ((size_t)s*128 + o)*64 + (c & 63);
        g_wAhi[di] = hi;
        g_wAlo[di] = __float2bfloat16_rn(lo);
    }
}

// ---------------------------------------------------------------------------
// Kernel 1: fused offset+mask conv (27 out ch, 3x3, pad 1) — FFMA2 path
// ---------------------------------------------------------------------------
__global__ __launch_bounds__(128) void offmask_kernel(
    const float* __restrict__ x,
    const float* __restrict__ w_off,  const float* __restrict__ b_off,
    const float* __restrict__ w_mask, const float* __restrict__ b_mask)
{
    __shared__ ull wsm[16*243];

    const int b   = blockIdx.y;
    const int tid = threadIdx.x;
    const int r   = tid >> 5;
    const int pg  = tid & 31;
    const int h_  = blockIdx.x*4 + r;
    const int p0  = pg*2;

    ull acc[27];
    #pragma unroll
    for (int i = 0; i < 27; i++) acc[i] = 0ull;

    const float* xb = x + (size_t)b*CIN*HH*WW;

    for (int chunk = 0; chunk < 8; chunk++){
        __syncthreads();
        const int c0 = chunk*16;
        for (int i = tid; i < 16*243; i += 128){
            int cl = i/243, j = i - cl*243;
            int oc = j/9,  k = j - oc*9;
            int c  = c0 + cl;
            float wv = (oc < 18) ? w_off[((size_t)oc*CIN + c)*9 + k]
                                 : w_mask[((size_t)(oc-18)*CIN + c)*9 + k];
            wsm[i] = pk2s(wv);
        }
        __syncthreads();

        for (int cl = 0; cl < 16; cl++){
            const float* xc = xb + (size_t)(c0+cl)*HH*WW;
            ull xp[3][3];
            #pragma unroll
            for (int rr = 0; rr < 3; rr++){
                int y = h_ - 1 + rr;
                bool vy = ((unsigned)y < (unsigned)HH);
                const float* xr = xc + y*WW;
                float v0 = (vy && pg > 0 ) ? xr[p0-1] : 0.f;
                float v1 =  vy             ? xr[p0  ] : 0.f;
                float v2 =  vy             ? xr[p0+1] : 0.f;
                float v3 = (vy && pg < 31) ? xr[p0+2] : 0.f;
                xp[rr][0] = pk2(v0, v1);
                xp[rr][1] = pk2(v1, v2);
                xp[rr][2] = pk2(v2, v3);
            }
            const ull* wc = wsm + cl*243;
            #pragma unroll
            for (int oc = 0; oc < 27; oc++){
                #pragma unroll
                for (int rr = 0; rr < 3; rr++){
                    #pragma unroll
                    for (int kx = 0; kx < 3; kx++){
                        acc[oc] = f2fma(wc[oc*9 + rr*3 + kx], xp[rr][kx], acc[oc]);
                    }
                }
            }
        }
    }

    #pragma unroll
    for (int oc = 0; oc < 27; oc++){
        union { ull u; float2 f; } cv; cv.u = acc[oc];
        float bias = (oc < 18) ? b_off[oc] : b_mask[oc-18];
        float a = cv.f.x + bias;
        float c = cv.f.y + bias;
        if (oc >= 18){
            a = 1.f/(1.f + __expf(-a));
            c = 1.f/(1.f + __expf(-c));
        }
        cv.f.x = a; cv.f.y = c;
        *reinterpret_cast<ull*>(&g_offmask[(((size_t)b*27 + oc)*HH + h_)*WW + p0]) = cv.u;
    }
}

// ---------------------------------------------------------------------------
// Kernel 2: deform gather + mma.sync bf16 (3-pass hi/lo split),
// warp-specialized: warps 0-7 produce (gather B + cp.async A),
// warps 8-15 consume (ldmatrix + MMA). 3-stage ring, named-barrier sync.
// Block = (b, 2 h-rows): D[128 o][128 px], K=1152 in 18 stages of 64.
// ---------------------------------------------------------------------------
#define N_STAGE  3
#define OFF_WT   0                       // 4*1152 floats  = 18432 B
#define OFF_AI   18432                   // 4*1152 int16   =  9216 B
#define OFF_STG  27648                   // stages
#define STG_SZ   65536                   // Ahi 16K | Alo 16K | Bhi 16K | Blo 16K
#define DSM_BYTES (OFF_STG + N_STAGE*STG_SZ)   // 224256

// barrier ids: full[st] = 1+st, empty[st] = 4+st
__device__ __forceinline__ void gather_stage(
    char* bufB_hi, const float* xb,
    const float* s_wt, const short* s_ai, int n_tap, int half, int ptid)
{
    const int p  = ptid & 127;
    const int cg = ptid >> 7;           // 0/1 → 32-channel half of the 64
    const int ci = n_tap*128 + p;
    const float w00 = s_wt[ci],      w01 = s_wt[1152+ci];
    const float w10 = s_wt[2304+ci], w11 = s_wt[3456+ci];
    const int a00 = s_ai[ci],      a01 = s_ai[1152+ci];
    const int a10 = s_ai[2304+ci], a11 = s_ai[3456+ci];
    const float* xp = xb + (size_t)(half*64 + cg*32)*(HH*WW);
    const int prow = p*128;
    const int psw  = p & 7;

    #pragma unroll
    for (int g = 0; g < 4; g++){        // 8 channels -> one 16B chunk
        uint32_t hi[4], lo[4];
        #pragma unroll
        for (int e = 0; e < 4; e++){
            const float* xc0 = xp + (size_t)(g*8 + e*2)*(HH*WW);
            const float* xc1 = xc0 + HH*WW;
            float v0 = w00*xc0[a00] + w01*xc0[a01] + w10*xc0[a10] + w11*xc0[a11];
            float v1 = w00*xc1[a00] + w01*xc1[a01] + w10*xc1[a10] + w11*xc1[a11];
            __nv_bfloat16 h0 = __float2bfloat16_rn(v0);
            __nv_bfloat16 h1 = __float2bfloat16_rn(v1);
            float r0 = v0 - __bfloat162float(h0);
            float r1 = v1 - __bfloat162float(h1);
            hi[e] = ((uint32_t)__bfloat16_as_ushort(h1) << 16) | __bfloat16_as_ushort(h0);
            lo[e] = pack_bf2(r0, r1);
        }
        int chunk = cg*4 + g;
        uint32_t off = prow + (uint32_t)((chunk ^ psw) << 4);
        *(uint4*)(bufB_hi + off)         = make_uint4(hi[0], hi[1], hi[2], hi[3]);
        *(uint4*)(bufB_hi + 16384 + off) = make_uint4(lo[0], lo[1], lo[2], lo[3]);
    }
}

__device__ __forceinline__ void cpasync_A(uint32_t bufA_u32, int stage_s, int ptid)
{
    const __nv_bfloat16* srcHi = g_wAhi + (size_t)stage_s*128*64;
    const __nv_bfloat16* srcLo = g_wAlo + (size_t)stage_s*128*64;
    #pragma unroll
    for (int r = 0; r < 4; r++){
        int id = r*256 + ptid;          // 0..1023
        int o = id >> 3, q = id & 7;
        uint32_t dst = bufA_u32 + (uint32_t)(o*128 + ((q ^ (o & 7)) << 4));
        CP_ASYNC16(dst,         srcHi + (size_t)o*64 + q*8);
        CP_ASYNC16(dst + 16384, srcLo + (size_t)o*64 + q*8);
    }
}

__device__ __forceinline__ void mma_stage(
    uint32_t sA, uint32_t sB, float acc[2][8][4], int wm, int wn, int lane)
{
    const int ar  = (lane & 7) + (((lane >> 3) & 1) << 3);  // m within 16
    const int akh = (lane >> 4) & 1;
    const int o0  = wm*32 + ar;
    const int o1  = o0 + 16;
    const int br  = (lane & 7) + (((lane >> 4) & 1) << 3);  // n within 16
    const int bkh = (lane >> 3) & 1;

    #pragma unroll
    for (int ks = 0; ks < 4; ks++){
        uint32_t ahi0[4], ahi1[4], alo0[4], alo1[4];
        {
            int ca = ks*2 + akh;
            uint32_t off0 = (uint32_t)(o0*128 + ((ca ^ (o0 & 7)) << 4));
            uint32_t off1 = (uint32_t)(o1*128 + ((ca ^ (o1 & 7)) << 4));
            LDMX4(ahi0, sA + off0);
            LDMX4(ahi1, sA + off1);
            LDMX4(alo0, sA + 16384 + off0);
            LDMX4(alo1, sA + 16384 + off1);
        }
        const int cb = ks*2 + bkh;
        #pragma unroll
        for (int g = 0; g < 4; g++){
            int pr = wn*64 + g*16 + br;
            uint32_t off = (uint32_t)(pr*128 + ((cb ^ (pr & 7)) << 4));
            uint32_t th[4], tl[4];
            LDMX4(th, sB + off);
            LDMX4(tl, sB + 16384 + off);
            #pragma unroll
            for (int sub = 0; sub < 2; sub++){
                int nf = g*2 + sub;
                MMA16816(acc[0][nf], ahi0[0],ahi0[1],ahi0[2],ahi0[3], th[2*sub], th[2*sub+1]);
                MMA16816(acc[1][nf], ahi1[0],ahi1[1],ahi1[2],ahi1[3], th[2*sub], th[2*sub+1]);
                MMA16816(acc[0][nf], alo0[0],alo0[1],alo0[2],alo0[3], th[2*sub], th[2*sub+1]);
                MMA16816(acc[1][nf], alo1[0],alo1[1],alo1[2],alo1[3], th[2*sub], th[2*sub+1]);
                MMA16816(acc[0][nf], ahi0[0],ahi0[1],ahi0[2],ahi0[3], tl[2*sub], tl[2*sub+1]);
                MMA16816(acc[1][nf], ahi1[0],ahi1[1],ahi1[2],ahi1[3], tl[2*sub], tl[2*sub+1]);
            }
        }
    }
}

__global__ __launch_bounds__(512) void deform_kernel(
    const float* __restrict__ x, float* __restrict__ out)
{
    extern __shared__ char dsm[];
    float* s_wt = (float*)(dsm + OFF_WT);
    short* s_ai = (short*)(dsm + OFF_AI);
    const uint32_t u_base = smem_u32(dsm);
    const uint32_t u_stg  = u_base + OFF_STG;

    const int tid  = threadIdx.x;
    const int wid  = tid >> 5;
    const int lane = tid & 31;
    const int h0   = blockIdx.x * 2;
    const int b    = blockIdx.y;

    // ---- corner tables for all (tap n, px) — all 512 threads ----
    const float* om = g_offmask + (size_t)b*27*HH*WW;
    for (int i = tid; i < 1152; i += 512){
        int n = i >> 7, rr = i & 127;
        int hh = rr >> 6, p = rr & 63;
        int h_ = h0 + hh;
        float offy = om[((size_t)(2*n  )*HH + h_)*WW + p];
        float offx = om[((size_t)(2*n+1)*HH + h_)*WW + p];
        float m    = om[((size_t)(18+n )*HH + h_)*WW + p];
        float py = offy + (float)(h_ - 1 + n/3);
        float px = offx + (float)(p  - 1 + n%3);
        float fy = floorf(py), fx = floorf(px);
        int y0 = (int)fy, x0 = (int)fx;
        float ly = py - fy, lx = px - fx;
        float hy = 1.f - ly, hx = 1.f - lx;
        int y1 = y0 + 1, x1 = x0 + 1;
        float vy0 = ((unsigned)y0 < 64u) ? 1.f : 0.f;
        float vy1 = ((unsigned)y1 < 64u) ? 1.f : 0.f;
        float vx0 = ((unsigned)x0 < 64u) ? 1.f : 0.f;
        float vx1 = ((unsigned)x1 < 64u) ? 1.f : 0.f;
        int y0c = min(max(y0,0),63), y1c = min(max(y1,0),63);
        int x0c = min(max(x0,0),63), x1c = min(max(x1,0),63);
        s_wt[0*1152 + i] = m*hy*hx*vy0*vx0;
        s_wt[1*1152 + i] = m*hy*lx*vy0*vx1;
        s_wt[2*1152 + i] = m*ly*hx*vy1*vx0;
        s_wt[3*1152 + i] = m*ly*lx*vy1*vx1;
        s_ai[0*1152 + i] = (short)(y0c*WW + x0c);
        s_ai[1*1152 + i] = (short)(y0c*WW + x1c);
        s_ai[2*1152 + i] = (short)(y1c*WW + x0c);
        s_ai[3*1152 + i] = (short)(y1c*WW + x1c);
    }
    __syncthreads();

    const float* xb = x + (size_t)b*CIN*HH*WW;

    if (wid < 8){
        // ================= PRODUCERS (warps 0-7) =================
        const int ptid = tid;           // 0..255
        for (int s = 0; s < 18; s++){
            const int st = s % N_STAGE;
            if (s >= N_STAGE) BAR_SYNC(4 + st);            // wait empty
            const uint32_t uc = u_stg + (uint32_t)st*STG_SZ;
            cpasync_A(uc, s, ptid);
            CP_COMMIT();
            gather_stage(dsm + OFF_STG + st*STG_SZ + 32768, xb, s_wt, s_ai,
                         s >> 1, s & 1, ptid);
            CP_WAIT0();
            BAR_ARRIVE(1 + st);                            // signal full
        }
    } else {
        // ================= CONSUMERS (warps 8-15) =================
        const int cwid = wid - 8;
        const int wm   = cwid & 3;
        const int wn   = cwid >> 2;

        float acc[2][8][4];
        #pragma unroll
        for (int a = 0; a < 2; a++)
            #pragma unroll
            for (int f = 0; f < 8; f++)
                #pragma unroll
                for (int e = 0; e < 4; e++) acc[a][f][e] = 0.f;

        for (int s = 0; s < 18; s++){
            const int st = s % N_STAGE;
            BAR_SYNC(1 + st);                              // wait full
            const uint32_t uc = u_stg + (uint32_t)st*STG_SZ;
            mma_stage(uc, uc + 32768, acc, wm, wn, lane);
            if (s < 18 - N_STAGE) BAR_ARRIVE(4 + st);      // signal empty
        }

        // ---- epilogue: D[o][px] -> out[b][o][h0+wn][w] ----
        const int h_ = h0 + wn;
        #pragma unroll
        for (int mf = 0; mf < 2; mf++){
            int o = wm*32 + mf*16 + (lane >> 2);
            float* p0 = out + (((size_t)b*COUT + o    )*HH + h_)*WW;
            float* p1 = out + (((size_t)b*COUT + o + 8)*HH + h_)*WW;
            #pragma unroll
            for (int nf = 0; nf < 8; nf++){
                int w = nf*8 + 2*(lane & 3);
                *(float2*)(p0 + w) = make_float2(acc[mf][nf][0], acc[mf][nf][1]);
                *(float2*)(p1 + w) = make_float2(acc[mf][nf][2], acc[mf][nf][3]);
            }
        }
    }
}

// ---------------------------------------------------------------------------
extern "C" void kernel_launch(void* const* d_in, const int* in_sizes, int n_in,
                              void* d_out, int out_size)
{
    const float* x      = (const float*)d_in[0];
    const float* w_conv = (const float*)d_in[1];
    const float* w_off  = (const float*)d_in[2];
    const float* b_off  = (const float*)d_in[3];
    const float* w_mask = (const float*)d_in[4];
    const float* b_mask = (const float*)d_in[5];
    float* out = (float*)d_out;

    cudaFuncSetAttribute(deform_kernel,
                         cudaFuncAttributeMaxDynamicSharedMemorySize, DSM_BYTES);

    prep_w_kernel<<<(9*128*128 + 255)/256, 256>>>(w_conv);
    offmask_kernel<<<dim3(16, 16), 128>>>(x, w_off, b_off, w_mask, b_mask);
    deform_kernel<<<dim3(32, 16), 512, DSM_BYTES>>>(x, out);
}

// round 6
// speedup vs baseline: 1.7817x; 1.0960x over previous
#include <cuda_runtime.h>
#include <cuda_fp16.h>
#include <cstdint>

#define BATCH 16
#define CIN   128
#define COUT  128
#define HH    64
#define WW    64

// ---------------------------------------------------------------------------
// Scratch (device globals: allocation-free rule)
// ---------------------------------------------------------------------------
__device__ float g_offmask[(size_t)BATCH*27*HH*WW]; // [b][27][h][w]; 0..17 offsets, 18..26 sigmoid(mask)
// Weights pre-split to fp16 hi/lo, layout [stage s = n*2+half][o:128][k:64]
__device__ __half g_wAhi[18*128*64];
__device__ __half g_wAlo[18*128*64];

typedef unsigned long long ull;

// ---------------------------------------------------------------------------
// Helpers
// ---------------------------------------------------------------------------
__device__ __forceinline__ uint32_t smem_u32(const void* p){
    uint32_t a;
    asm("{ .reg .u64 t; cvta.to.shared.u64 t, %1; cvt.u32.u64 %0, t; }" : "=r"(a) : "l"(p));
    return a;
}

#define LDMX4(r, addr) \
    asm volatile("ldmatrix.sync.aligned.m8n8.x4.shared.b16 {%0,%1,%2,%3}, [%4];" \
        : "=r"((r)[0]), "=r"((r)[1]), "=r"((r)[2]), "=r"((r)[3]) : "r"(addr))

#define MMA16816(d, a0, a1, a2, a3, b0, b1) \
    asm volatile("mma.sync.aligned.m16n8k16.row.col.f32.f16.f16.f32 " \
        "{%0,%1,%2,%3}, {%4,%5,%6,%7}, {%8,%9}, {%0,%1,%2,%3};" \
        : "+f"((d)[0]), "+f"((d)[1]), "+f"((d)[2]), "+f"((d)[3]) \
        : "r"(a0), "r"(a1), "r"(a2), "r"(a3), "r"(b0), "r"(b1))

#define CP_ASYNC16(dst, src) \
    asm volatile("cp.async.ca.shared.global [%0], [%1], 16;" :: "r"(dst), "l"(src))
#define CP_COMMIT()  asm volatile("cp.async.commit_group;" ::: "memory")
#define CP_WAIT0()   asm volatile("cp.async.wait_group 0;" ::: "memory")

// Named-barrier producer/consumer sync (512 threads total per pair)
#define BAR_SYNC(id)   asm volatile("bar.sync %0, 512;"   :: "r"(id) : "memory")
#define BAR_ARRIVE(id) asm volatile("bar.arrive %0, 512;" :: "r"(id) : "memory")

__device__ __forceinline__ uint32_t pack_h2(float v0, float v1){
    __half h0 = __float2half_rn(v0);
    __half h1 = __float2half_rn(v1);
    return ((uint32_t)__half_as_ushort(h1) << 16) | __half_as_ushort(h0);
}

// FFMA2 helpers for offmask kernel
__device__ __forceinline__ ull pk2(float a, float b){
    ull r; asm("mov.b64 %0, {%1, %2};" : "=l"(r) : "f"(a), "f"(b)); return r;
}
__device__ __forceinline__ ull pk2s(float a){
    ull r; asm("mov.b64 %0, {%1, %1};" : "=l"(r) : "f"(a)); return r;
}
__device__ __forceinline__ ull f2fma(ull a, ull b, ull c){
    ull d; asm("fma.rn.f32x2 %0, %1, %2, %3;" : "=l"(d) : "l"(a), "l"(b), "l"(c)); return d;
}

// ---------------------------------------------------------------------------
// Kernel 0: split w_conv [o][c][n] into fp16 hi/lo, layout [s=n*2+c/64][o][c%64]
// ---------------------------------------------------------------------------
__global__ void prep_w_kernel(const float* __restrict__ w_conv){
    int i = blockIdx.x * blockDim.x + threadIdx.x;
    if (i < 9*128*128){
        int n = i / (128*128);
        int o = (i >> 7) & 127;
        int c = i & 127;
        float w = w_conv[((size_t)o*128 + c)*9 + n];
        __half hi = __float2half_rn(w);
        float lo = w - __half2float(hi);
        int s = n*2 + (c >> 6);
        size_t di = ((size_t)s*128 + o)*64 + (c & 63);
        g_wAhi[di] = hi;
        g_wAlo[di] = __float2half_rn(lo);
    }
}

// ---------------------------------------------------------------------------
// Kernel 1: fused offset+mask conv (27 out ch, 3x3, pad 1) — FFMA2 path
// ---------------------------------------------------------------------------
__global__ __launch_bounds__(128) void offmask_kernel(
    const float* __restrict__ x,
    const float* __restrict__ w_off,  const float* __restrict__ b_off,
    const float* __restrict__ w_mask, const float* __restrict__ b_mask)
{
    __shared__ ull wsm[16*243];

    const int b   = blockIdx.y;
    const int tid = threadIdx.x;
    const int r   = tid >> 5;
    const int pg  = tid & 31;
    const int h_  = blockIdx.x*4 + r;
    const int p0  = pg*2;

    ull acc[27];
    #pragma unroll
    for (int i = 0; i < 27; i++) acc[i] = 0ull;

    const float* xb = x + (size_t)b*CIN*HH*WW;

    for (int chunk = 0; chunk < 8; chunk++){
        __syncthreads();
        const int c0 = chunk*16;
        for (int i = tid; i < 16*243; i += 128){
            int cl = i/243, j = i - cl*243;
            int oc = j/9,  k = j - oc*9;
            int c  = c0 + cl;
            float wv = (oc < 18) ? w_off[((size_t)oc*CIN + c)*9 + k]
                                 : w_mask[((size_t)(oc-18)*CIN + c)*9 + k];
            wsm[i] = pk2s(wv);
        }
        __syncthreads();

        for (int cl = 0; cl < 16; cl++){
            const float* xc = xb + (size_t)(c0+cl)*HH*WW;
            ull xp[3][3];
            #pragma unroll
            for (int rr = 0; rr < 3; rr++){
                int y = h_ - 1 + rr;
                bool vy = ((unsigned)y < (unsigned)HH);
                const float* xr = xc + y*WW;
                float v0 = (vy && pg > 0 ) ? xr[p0-1] : 0.f;
                float v1 =  vy             ? xr[p0  ] : 0.f;
                float v2 =  vy             ? xr[p0+1] : 0.f;
                float v3 = (vy && pg < 31) ? xr[p0+2] : 0.f;
                xp[rr][0] = pk2(v0, v1);
                xp[rr][1] = pk2(v1, v2);
                xp[rr][2] = pk2(v2, v3);
            }
            const ull* wc = wsm + cl*243;
            #pragma unroll
            for (int oc = 0; oc < 27; oc++){
                #pragma unroll
                for (int rr = 0; rr < 3; rr++){
                    #pragma unroll
                    for (int kx = 0; kx < 3; kx++){
                        acc[oc] = f2fma(wc[oc*9 + rr*3 + kx], xp[rr][kx], acc[oc]);
                    }
                }
            }
        }
    }

    #pragma unroll
    for (int oc = 0; oc < 27; oc++){
        union { ull u; float2 f; } cv; cv.u = acc[oc];
        float bias = (oc < 18) ? b_off[oc] : b_mask[oc-18];
        float a = cv.f.x + bias;
        float c = cv.f.y + bias;
        if (oc >= 18){
            a = 1.f/(1.f + __expf(-a));
            c = 1.f/(1.f + __expf(-c));
        }
        cv.f.x = a; cv.f.y = c;
        *reinterpret_cast<ull*>(&g_offmask[(((size_t)b*27 + oc)*HH + h_)*WW + p0]) = cv.u;
    }
}

// ---------------------------------------------------------------------------
// Kernel 2: deform gather + mma.sync fp16 (2-pass: A hi/lo exact, B single rn)
// warp-specialized: warps 0-7 produce (gather B + cp.async A),
// warps 8-15 consume (ldmatrix + MMA). 4-stage ring, named-barrier sync.
// Block = (b, 2 h-rows): D[128 o][128 px], K=1152 in 18 stages of 64.
// ---------------------------------------------------------------------------
#define N_STAGE  4
#define OFF_WT   0                       // 4*1152 floats  = 18432 B
#define OFF_AI   18432                   // 4*1152 int16   =  9216 B
#define OFF_STG  27648                   // stages
#define STG_SZ   49152                   // Ahi 16K | Alo 16K | B 16K
#define DSM_BYTES (OFF_STG + N_STAGE*STG_SZ)   // 224256

// barrier ids: full[st] = 1+st (1..4), empty[st] = 5+st (5..8)
__device__ __forceinline__ void gather_stage(
    char* bufB, const float* xb,
    const float* s_wt, const short* s_ai, int n_tap, int half, int ptid)
{
    const int p  = ptid & 127;
    const int cg = ptid >> 7;           // 0/1 → 32-channel half of the 64
    const int ci = n_tap*128 + p;
    const float w00 = s_wt[ci],      w01 = s_wt[1152+ci];
    const float w10 = s_wt[2304+ci], w11 = s_wt[3456+ci];
    const int a00 = s_ai[ci],      a01 = s_ai[1152+ci];
    const int a10 = s_ai[2304+ci], a11 = s_ai[3456+ci];
    const float* xp = xb + (size_t)(half*64 + cg*32)*(HH*WW);
    const int prow = p*128;
    const int psw  = p & 7;

    #pragma unroll
    for (int g = 0; g < 4; g++){        // 8 channels -> one 16B chunk
        uint32_t hv[4];
        #pragma unroll
        for (int e = 0; e < 4; e++){
            const float* xc0 = xp + (size_t)(g*8 + e*2)*(HH*WW);
            const float* xc1 = xc0 + HH*WW;
            float v0 = w00*xc0[a00] + w01*xc0[a01] + w10*xc0[a10] + w11*xc0[a11];
            float v1 = w00*xc1[a00] + w01*xc1[a01] + w10*xc1[a10] + w11*xc1[a11];
            hv[e] = pack_h2(v0, v1);
        }
        int chunk = cg*4 + g;
        uint32_t off = prow + (uint32_t)((chunk ^ psw) << 4);
        *(uint4*)(bufB + off) = make_uint4(hv[0], hv[1], hv[2], hv[3]);
    }
}

__device__ __forceinline__ void cpasync_A(uint32_t bufA_u32, int stage_s, int ptid)
{
    const __half* srcHi = g_wAhi + (size_t)stage_s*128*64;
    const __half* srcLo = g_wAlo + (size_t)stage_s*128*64;
    #pragma unroll
    for (int r = 0; r < 4; r++){
        int id = r*256 + ptid;          // 0..1023
        int o = id >> 3, q = id & 7;
        uint32_t dst = bufA_u32 + (uint32_t)(o*128 + ((q ^ (o & 7)) << 4));
        CP_ASYNC16(dst,         srcHi + (size_t)o*64 + q*8);
        CP_ASYNC16(dst + 16384, srcLo + (size_t)o*64 + q*8);
    }
}

__device__ __forceinline__ void mma_stage(
    uint32_t sA, uint32_t sB, float acc[2][8][4], int wm, int wn, int lane)
{
    const int ar  = (lane & 7) + (((lane >> 3) & 1) << 3);  // m within 16
    const int akh = (lane >> 4) & 1;
    const int o0  = wm*32 + ar;
    const int o1  = o0 + 16;
    const int br  = (lane & 7) + (((lane >> 4) & 1) << 3);  // n within 16
    const int bkh = (lane >> 3) & 1;

    #pragma unroll
    for (int ks = 0; ks < 4; ks++){
        uint32_t ahi0[4], ahi1[4], alo0[4], alo1[4];
        {
            int ca = ks*2 + akh;
            uint32_t off0 = (uint32_t)(o0*128 + ((ca ^ (o0 & 7)) << 4));
            uint32_t off1 = (uint32_t)(o1*128 + ((ca ^ (o1 & 7)) << 4));
            LDMX4(ahi0, sA + off0);
            LDMX4(ahi1, sA + off1);
            LDMX4(alo0, sA + 16384 + off0);
            LDMX4(alo1, sA + 16384 + off1);
        }
        const int cb = ks*2 + bkh;
        #pragma unroll
        for (int g = 0; g < 4; g++){
            int pr = wn*64 + g*16 + br;
            uint32_t off = (uint32_t)(pr*128 + ((cb ^ (pr & 7)) << 4));
            uint32_t th[4];
            LDMX4(th, sB + off);
            #pragma unroll
            for (int sub = 0; sub < 2; sub++){
                int nf = g*2 + sub;
                MMA16816(acc[0][nf], ahi0[0],ahi0[1],ahi0[2],ahi0[3], th[2*sub], th[2*sub+1]);
                MMA16816(acc[1][nf], ahi1[0],ahi1[1],ahi1[2],ahi1[3], th[2*sub], th[2*sub+1]);
                MMA16816(acc[0][nf], alo0[0],alo0[1],alo0[2],alo0[3], th[2*sub], th[2*sub+1]);
                MMA16816(acc[1][nf], alo1[0],alo1[1],alo1[2],alo1[3], th[2*sub], th[2*sub+1]);
            }
        }
    }
}

__global__ __launch_bounds__(512) void deform_kernel(
    const float* __restrict__ x, float* __restrict__ out)
{
    extern __shared__ char dsm[];
    float* s_wt = (float*)(dsm + OFF_WT);
    short* s_ai = (short*)(dsm + OFF_AI);
    const uint32_t u_base = smem_u32(dsm);
    const uint32_t u_stg  = u_base + OFF_STG;

    const int tid  = threadIdx.x;
    const int wid  = tid >> 5;
    const int lane = tid & 31;
    const int h0   = blockIdx.x * 2;
    const int b    = blockIdx.y;

    // ---- corner tables for all (tap n, px) — all 512 threads ----
    const float* om = g_offmask + (size_t)b*27*HH*WW;
    for (int i = tid; i < 1152; i += 512){
        int n = i >> 7, rr = i & 127;
        int hh = rr >> 6, p = rr & 63;
        int h_ = h0 + hh;
        float offy = om[((size_t)(2*n  )*HH + h_)*WW + p];
        float offx = om[((size_t)(2*n+1)*HH + h_)*WW + p];
        float m    = om[((size_t)(18+n )*HH + h_)*WW + p];
        float py = offy + (float)(h_ - 1 + n/3);
        float px = offx + (float)(p  - 1 + n%3);
        float fy = floorf(py), fx = floorf(px);
        int y0 = (int)fy, x0 = (int)fx;
        float ly = py - fy, lx = px - fx;
        float hy = 1.f - ly, hx = 1.f - lx;
        int y1 = y0 + 1, x1 = x0 + 1;
        float vy0 = ((unsigned)y0 < 64u) ? 1.f : 0.f;
        float vy1 = ((unsigned)y1 < 64u) ? 1.f : 0.f;
        float vx0 = ((unsigned)x0 < 64u) ? 1.f : 0.f;
        float vx1 = ((unsigned)x1 < 64u) ? 1.f : 0.f;
        int y0c = min(max(y0,0),63), y1c = min(max(y1,0),63);
        int x0c = min(max(x0,0),63), x1c = min(max(x1,0),63);
        s_wt[0*1152 + i] = m*hy*hx*vy0*vx0;
        s_wt[1*1152 + i] = m*hy*lx*vy0*vx1;
        s_wt[2*1152 + i] = m*ly*hx*vy1*vx0;
        s_wt[3*1152 + i] = m*ly*lx*vy1*vx1;
        s_ai[0*1152 + i] = (short)(y0c*WW + x0c);
        s_ai[1*1152 + i] = (short)(y0c*WW + x1c);
        s_ai[2*1152 + i] = (short)(y1c*WW + x0c);
        s_ai[3*1152 + i] = (short)(y1c*WW + x1c);
    }
    __syncthreads();

    const float* xb = x + (size_t)b*CIN*HH*WW;

    if (wid < 8){
        // ================= PRODUCERS (warps 0-7) =================
        const int ptid = tid;           // 0..255
        for (int s = 0; s < 18; s++){
            const int st = s % N_STAGE;
            if (s >= N_STAGE) BAR_SYNC(5 + st);            // wait empty
            const uint32_t uc = u_stg + (uint32_t)st*STG_SZ;
            cpasync_A(uc, s, ptid);
            CP_COMMIT();
            gather_stage(dsm + OFF_STG + st*STG_SZ + 32768, xb, s_wt, s_ai,
                         s >> 1, s & 1, ptid);
            CP_WAIT0();
            BAR_ARRIVE(1 + st);                            // signal full
        }
    } else {
        // ================= CONSUMERS (warps 8-15) =================
        const int cwid = wid - 8;
        const int wm   = cwid & 3;
        const int wn   = cwid >> 2;

        float acc[2][8][4];
        #pragma unroll
        for (int a = 0; a < 2; a++)
            #pragma unroll
            for (int f = 0; f < 8; f++)
                #pragma unroll
                for (int e = 0; e < 4; e++) acc[a][f][e] = 0.f;

        for (int s = 0; s < 18; s++){
            const int st = s % N_STAGE;
            BAR_SYNC(1 + st);                              // wait full
            const uint32_t uc = u_stg + (uint32_t)st*STG_SZ;
            mma_stage(uc, uc + 32768, acc, wm, wn, lane);
            if (s < 18 - N_STAGE) BAR_ARRIVE(5 + st);      // signal empty
        }

        // ---- epilogue: D[o][px] -> out[b][o][h0+wn][w] ----
        const int h_ = h0 + wn;
        #pragma unroll
        for (int mf = 0; mf < 2; mf++){
            int o = wm*32 + mf*16 + (lane >> 2);
            float* p0 = out + (((size_t)b*COUT + o    )*HH + h_)*WW;
            float* p1 = out + (((size_t)b*COUT + o + 8)*HH + h_)*WW;
            #pragma unroll
            for (int nf = 0; nf < 8; nf++){
                int w = nf*8 + 2*(lane & 3);
                *(float2*)(p0 + w) = make_float2(acc[mf][nf][0], acc[mf][nf][1]);
                *(float2*)(p1 + w) = make_float2(acc[mf][nf][2], acc[mf][nf][3]);
            }
        }
    }
}

// ---------------------------------------------------------------------------
extern "C" void kernel_launch(void* const* d_in, const int* in_sizes, int n_in,
                              void* d_out, int out_size)
{
    const float* x      = (const float*)d_in[0];
    const float* w_conv = (const float*)d_in[1];
    const float* w_off  = (const float*)d_in[2];
    const float* b_off  = (const float*)d_in[3];
    const float* w_mask = (const float*)d_in[4];
    const float* b_mask = (const float*)d_in[5];
    float* out = (float*)d_out;

    cudaFuncSetAttribute(deform_kernel,
                         cudaFuncAttributeMaxDynamicSharedMemorySize, DSM_BYTES);

    prep_w_kernel<<<(9*128*128 + 255)/256, 256>>>(w_conv);
    offmask_kernel<<<dim3(16, 16), 128>>>(x, w_off, b_off, w_mask, b_mask);
    deform_kernel<<<dim3(32, 16), 512, DSM_BYTES>>>(x, out);
}

// round 7
// speedup vs baseline: 1.8987x; 1.0657x over previous
#include <cuda_runtime.h>
#include <cuda_fp16.h>
#include <cstdint>

#define BATCH 16
#define CIN   128
#define COUT  128
#define HH    64
#define WW    64

// ---------------------------------------------------------------------------
// Scratch (device globals: allocation-free rule)
// ---------------------------------------------------------------------------
__device__ float g_offmask[(size_t)BATCH*27*HH*WW]; // [b][27][h][w]; 0..17 offsets, 18..26 sigmoid(mask)
// Weights as fp16 (rn), layout [stage s = n*2+half][o:128][k:64]
__device__ __half g_wA[18*128*64];

typedef unsigned long long ull;

// ---------------------------------------------------------------------------
// Helpers
// ---------------------------------------------------------------------------
__device__ __forceinline__ uint32_t smem_u32(const void* p){
    uint32_t a;
    asm("{ .reg .u64 t; cvta.to.shared.u64 t, %1; cvt.u32.u64 %0, t; }" : "=r"(a) : "l"(p));
    return a;
}

#define LDMX4(r, addr) \
    asm volatile("ldmatrix.sync.aligned.m8n8.x4.shared.b16 {%0,%1,%2,%3}, [%4];" \
        : "=r"((r)[0]), "=r"((r)[1]), "=r"((r)[2]), "=r"((r)[3]) : "r"(addr))

#define MMA16816(d, a0, a1, a2, a3, b0, b1) \
    asm volatile("mma.sync.aligned.m16n8k16.row.col.f32.f16.f16.f32 " \
        "{%0,%1,%2,%3}, {%4,%5,%6,%7}, {%8,%9}, {%0,%1,%2,%3};" \
        : "+f"((d)[0]), "+f"((d)[1]), "+f"((d)[2]), "+f"((d)[3]) \
        : "r"(a0), "r"(a1), "r"(a2), "r"(a3), "r"(b0), "r"(b1))

#define CP_ASYNC16(dst, src) \
    asm volatile("cp.async.ca.shared.global [%0], [%1], 16;" :: "r"(dst), "l"(src))
#define CP_COMMIT()  asm volatile("cp.async.commit_group;" ::: "memory")
#define CP_WAIT0()   asm volatile("cp.async.wait_group 0;" ::: "memory")

// Named-barrier producer/consumer sync (512 threads total per pair)
#define BAR_SYNC(id)   asm volatile("bar.sync %0, 512;"   :: "r"(id) : "memory")
#define BAR_ARRIVE(id) asm volatile("bar.arrive %0, 512;" :: "r"(id) : "memory")

__device__ __forceinline__ uint32_t pack_h2(float v0, float v1){
    __half h0 = __float2half_rn(v0);
    __half h1 = __float2half_rn(v1);
    return ((uint32_t)__half_as_ushort(h1) << 16) | __half_as_ushort(h0);
}

// FFMA2 helpers for offmask kernel
__device__ __forceinline__ ull pk2(float a, float b){
    ull r; asm("mov.b64 %0, {%1, %2};" : "=l"(r) : "f"(a), "f"(b)); return r;
}
__device__ __forceinline__ ull pk2s(float a){
    ull r; asm("mov.b64 %0, {%1, %1};" : "=l"(r) : "f"(a)); return r;
}
__device__ __forceinline__ ull f2fma(ull a, ull b, ull c){
    ull d; asm("fma.rn.f32x2 %0, %1, %2, %3;" : "=l"(d) : "l"(a), "l"(b), "l"(c)); return d;
}

// ---------------------------------------------------------------------------
// Kernel 0: round w_conv [o][c][n] to fp16, layout [s=n*2+c/64][o][c%64]
// ---------------------------------------------------------------------------
__global__ void prep_w_kernel(const float* __restrict__ w_conv){
    int i = blockIdx.x * blockDim.x + threadIdx.x;
    if (i < 9*128*128){
        int n = i / (128*128);
        int o = (i >> 7) & 127;
        int c = i & 127;
        float w = w_conv[((size_t)o*128 + c)*9 + n];
        int s = n*2 + (c >> 6);
        size_t di = ((size_t)s*128 + o)*64 + (c & 63);
        g_wA[di] = __float2half_rn(w);
    }
}

// ---------------------------------------------------------------------------
// Kernel 1: fused offset+mask conv (27 out ch, 3x3, pad 1) — FFMA2 path
// ---------------------------------------------------------------------------
__global__ __launch_bounds__(128) void offmask_kernel(
    const float* __restrict__ x,
    const float* __restrict__ w_off,  const float* __restrict__ b_off,
    const float* __restrict__ w_mask, const float* __restrict__ b_mask)
{
    __shared__ ull wsm[16*243];

    const int b   = blockIdx.y;
    const int tid = threadIdx.x;
    const int r   = tid >> 5;
    const int pg  = tid & 31;
    const int h_  = blockIdx.x*4 + r;
    const int p0  = pg*2;

    ull acc[27];
    #pragma unroll
    for (int i = 0; i < 27; i++) acc[i] = 0ull;

    const float* xb = x + (size_t)b*CIN*HH*WW;

    for (int chunk = 0; chunk < 8; chunk++){
        __syncthreads();
        const int c0 = chunk*16;
        for (int i = tid; i < 16*243; i += 128){
            int cl = i/243, j = i - cl*243;
            int oc = j/9,  k = j - oc*9;
            int c  = c0 + cl;
            float wv = (oc < 18) ? w_off[((size_t)oc*CIN + c)*9 + k]
                                 : w_mask[((size_t)(oc-18)*CIN + c)*9 + k];
            wsm[i] = pk2s(wv);
        }
        __syncthreads();

        for (int cl = 0; cl < 16; cl++){
            const float* xc = xb + (size_t)(c0+cl)*HH*WW;
            ull xp[3][3];
            #pragma unroll
            for (int rr = 0; rr < 3; rr++){
                int y = h_ - 1 + rr;
                bool vy = ((unsigned)y < (unsigned)HH);
                const float* xr = xc + y*WW;
                float v0 = (vy && pg > 0 ) ? xr[p0-1] : 0.f;
                float v1 =  vy             ? xr[p0  ] : 0.f;
                float v2 =  vy             ? xr[p0+1] : 0.f;
                float v3 = (vy && pg < 31) ? xr[p0+2] : 0.f;
                xp[rr][0] = pk2(v0, v1);
                xp[rr][1] = pk2(v1, v2);
                xp[rr][2] = pk2(v2, v3);
            }
            const ull* wc = wsm + cl*243;
            #pragma unroll
            for (int oc = 0; oc < 27; oc++){
                #pragma unroll
                for (int rr = 0; rr < 3; rr++){
                    #pragma unroll
                    for (int kx = 0; kx < 3; kx++){
                        acc[oc] = f2fma(wc[oc*9 + rr*3 + kx], xp[rr][kx], acc[oc]);
                    }
                }
            }
        }
    }

    #pragma unroll
    for (int oc = 0; oc < 27; oc++){
        union { ull u; float2 f; } cv; cv.u = acc[oc];
        float bias = (oc < 18) ? b_off[oc] : b_mask[oc-18];
        float a = cv.f.x + bias;
        float c = cv.f.y + bias;
        if (oc >= 18){
            a = 1.f/(1.f + __expf(-a));
            c = 1.f/(1.f + __expf(-c));
        }
        cv.f.x = a; cv.f.y = c;
        *reinterpret_cast<ull*>(&g_offmask[(((size_t)b*27 + oc)*HH + h_)*WW + p0]) = cv.u;
    }
}

// ---------------------------------------------------------------------------
// Kernel 2: deform gather + mma.sync fp16 single-pass (A rn, B rn)
// warp-specialized: warps 0-7 produce (gather B + cp.async A),
// warps 8-15 consume (ldmatrix + MMA). 6-stage ring, named-barrier sync.
// Block = (b, 2 h-rows): D[128 o][128 px], K=1152 in 18 stages of 64.
// ---------------------------------------------------------------------------
#define N_STAGE  6
#define OFF_WT   0                       // 4*1152 floats  = 18432 B
#define OFF_AI   18432                   // 4*1152 int16   =  9216 B
#define OFF_STG  27648                   // stages
#define STG_SZ   32768                   // A 16K | B 16K
#define DSM_BYTES (OFF_STG + N_STAGE*STG_SZ)   // 224256

// barrier ids: full[st] = 1+st (1..6), empty[st] = 7+st (7..12)
__device__ __forceinline__ void gather_stage(
    char* bufB, const float* xb,
    const float* s_wt, const short* s_ai, int n_tap, int half, int ptid)
{
    const int p  = ptid & 127;
    const int cg = ptid >> 7;           // 0/1 → 32-channel half of the 64
    const int ci = n_tap*128 + p;
    const float w00 = s_wt[ci],      w01 = s_wt[1152+ci];
    const float w10 = s_wt[2304+ci], w11 = s_wt[3456+ci];
    const int a00 = s_ai[ci],      a01 = s_ai[1152+ci];
    const int a10 = s_ai[2304+ci], a11 = s_ai[3456+ci];
    const float* xp = xb + (size_t)(half*64 + cg*32)*(HH*WW);
    const int prow = p*128;
    const int psw  = p & 7;

    #pragma unroll
    for (int g = 0; g < 4; g++){        // 8 channels -> one 16B chunk
        uint32_t hv[4];
        #pragma unroll
        for (int e = 0; e < 4; e++){
            const float* xc0 = xp + (size_t)(g*8 + e*2)*(HH*WW);
            const float* xc1 = xc0 + HH*WW;
            float v0 = w00*xc0[a00] + w01*xc0[a01] + w10*xc0[a10] + w11*xc0[a11];
            float v1 = w00*xc1[a00] + w01*xc1[a01] + w10*xc1[a10] + w11*xc1[a11];
            hv[e] = pack_h2(v0, v1);
        }
        int chunk = cg*4 + g;
        uint32_t off = prow + (uint32_t)((chunk ^ psw) << 4);
        *(uint4*)(bufB + off) = make_uint4(hv[0], hv[1], hv[2], hv[3]);
    }
}

__device__ __forceinline__ void cpasync_A(uint32_t bufA_u32, int stage_s, int ptid)
{
    const __half* src = g_wA + (size_t)stage_s*128*64;
    #pragma unroll
    for (int r = 0; r < 4; r++){
        int id = r*256 + ptid;          // 0..1023
        int o = id >> 3, q = id & 7;
        uint32_t dst = bufA_u32 + (uint32_t)(o*128 + ((q ^ (o & 7)) << 4));
        CP_ASYNC16(dst, src + (size_t)o*64 + q*8);
    }
}

__device__ __forceinline__ void mma_stage(
    uint32_t sA, uint32_t sB, float acc[2][8][4], int wm, int wn, int lane)
{
    const int ar  = (lane & 7) + (((lane >> 3) & 1) << 3);  // m within 16
    const int akh = (lane >> 4) & 1;
    const int o0  = wm*32 + ar;
    const int o1  = o0 + 16;
    const int br  = (lane & 7) + (((lane >> 4) & 1) << 3);  // n within 16
    const int bkh = (lane >> 3) & 1;

    #pragma unroll
    for (int ks = 0; ks < 4; ks++){
        uint32_t a0[4], a1[4];
        {
            int ca = ks*2 + akh;
            uint32_t off0 = (uint32_t)(o0*128 + ((ca ^ (o0 & 7)) << 4));
            uint32_t off1 = (uint32_t)(o1*128 + ((ca ^ (o1 & 7)) << 4));
            LDMX4(a0, sA + off0);
            LDMX4(a1, sA + off1);
        }
        const int cb = ks*2 + bkh;
        #pragma unroll
        for (int g = 0; g < 4; g++){
            int pr = wn*64 + g*16 + br;
            uint32_t off = (uint32_t)(pr*128 + ((cb ^ (pr & 7)) << 4));
            uint32_t th[4];
            LDMX4(th, sB + off);
            #pragma unroll
            for (int sub = 0; sub < 2; sub++){
                int nf = g*2 + sub;
                MMA16816(acc[0][nf], a0[0],a0[1],a0[2],a0[3], th[2*sub], th[2*sub+1]);
                MMA16816(acc[1][nf], a1[0],a1[1],a1[2],a1[3], th[2*sub], th[2*sub+1]);
            }
        }
    }
}

__global__ __launch_bounds__(512) void deform_kernel(
    const float* __restrict__ x, float* __restrict__ out)
{
    extern __shared__ char dsm[];
    float* s_wt = (float*)(dsm + OFF_WT);
    short* s_ai = (short*)(dsm + OFF_AI);
    const uint32_t u_base = smem_u32(dsm);
    const uint32_t u_stg  = u_base + OFF_STG;

    const int tid  = threadIdx.x;
    const int wid  = tid >> 5;
    const int lane = tid & 31;
    const int h0   = blockIdx.x * 2;
    const int b    = blockIdx.y;

    // ---- corner tables for all (tap n, px) — all 512 threads ----
    const float* om = g_offmask + (size_t)b*27*HH*WW;
    for (int i = tid; i < 1152; i += 512){
        int n = i >> 7, rr = i & 127;
        int hh = rr >> 6, p = rr & 63;
        int h_ = h0 + hh;
        float offy = om[((size_t)(2*n  )*HH + h_)*WW + p];
        float offx = om[((size_t)(2*n+1)*HH + h_)*WW + p];
        float m    = om[((size_t)(18+n )*HH + h_)*WW + p];
        float py = offy + (float)(h_ - 1 + n/3);
        float px = offx + (float)(p  - 1 + n%3);
        float fy = floorf(py), fx = floorf(px);
        int y0 = (int)fy, x0 = (int)fx;
        float ly = py - fy, lx = px - fx;
        float hy = 1.f - ly, hx = 1.f - lx;
        int y1 = y0 + 1, x1 = x0 + 1;
        float vy0 = ((unsigned)y0 < 64u) ? 1.f : 0.f;
        float vy1 = ((unsigned)y1 < 64u) ? 1.f : 0.f;
        float vx0 = ((unsigned)x0 < 64u) ? 1.f : 0.f;
        float vx1 = ((unsigned)x1 < 64u) ? 1.f : 0.f;
        int y0c = min(max(y0,0),63), y1c = min(max(y1,0),63);
        int x0c = min(max(x0,0),63), x1c = min(max(x1,0),63);
        s_wt[0*1152 + i] = m*hy*hx*vy0*vx0;
        s_wt[1*1152 + i] = m*hy*lx*vy0*vx1;
        s_wt[2*1152 + i] = m*ly*hx*vy1*vx0;
        s_wt[3*1152 + i] = m*ly*lx*vy1*vx1;
        s_ai[0*1152 + i] = (short)(y0c*WW + x0c);
        s_ai[1*1152 + i] = (short)(y0c*WW + x1c);
        s_ai[2*1152 + i] = (short)(y1c*WW + x0c);
        s_ai[3*1152 + i] = (short)(y1c*WW + x1c);
    }
    __syncthreads();

    const float* xb = x + (size_t)b*CIN*HH*WW;

    if (wid < 8){
        // ================= PRODUCERS (warps 0-7) =================
        const int ptid = tid;           // 0..255
        for (int s = 0; s < 18; s++){
            const int st = s % N_STAGE;
            if (s >= N_STAGE) BAR_SYNC(7 + st);            // wait empty
            const uint32_t uc = u_stg + (uint32_t)st*STG_SZ;
            cpasync_A(uc, s, ptid);
            CP_COMMIT();
            gather_stage(dsm + OFF_STG + st*STG_SZ + 16384, xb, s_wt, s_ai,
                         s >> 1, s & 1, ptid);
            CP_WAIT0();
            BAR_ARRIVE(1 + st);                            // signal full
        }
    } else {
        // ================= CONSUMERS (warps 8-15) =================
        const int cwid = wid - 8;
        const int wm   = cwid & 3;
        const int wn   = cwid >> 2;

        float acc[2][8][4];
        #pragma unroll
        for (int a = 0; a < 2; a++)
            #pragma unroll
            for (int f = 0; f < 8; f++)
                #pragma unroll
                for (int e = 0; e < 4; e++) acc[a][f][e] = 0.f;

        for (int s = 0; s < 18; s++){
            const int st = s % N_STAGE;
            BAR_SYNC(1 + st);                              // wait full
            const uint32_t uc = u_stg + (uint32_t)st*STG_SZ;
            mma_stage(uc, uc + 16384, acc, wm, wn, lane);
            if (s < 18 - N_STAGE) BAR_ARRIVE(7 + st);      // signal empty
        }

        // ---- epilogue: D[o][px] -> out[b][o][h0+wn][w] ----
        const int h_ = h0 + wn;
        #pragma unroll
        for (int mf = 0; mf < 2; mf++){
            int o = wm*32 + mf*16 + (lane >> 2);
            float* p0 = out + (((size_t)b*COUT + o    )*HH + h_)*WW;
            float* p1 = out + (((size_t)b*COUT + o + 8)*HH + h_)*WW;
            #pragma unroll
            for (int nf = 0; nf < 8; nf++){
                int w = nf*8 + 2*(lane & 3);
                *(float2*)(p0 + w) = make_float2(acc[mf][nf][0], acc[mf][nf][1]);
                *(float2*)(p1 + w) = make_float2(acc[mf][nf][2], acc[mf][nf][3]);
            }
        }
    }
}

// ---------------------------------------------------------------------------
extern "C" void kernel_launch(void* const* d_in, const int* in_sizes, int n_in,
                              void* d_out, int out_size)
{
    const float* x      = (const float*)d_in[0];
    const float* w_conv = (const float*)d_in[1];
    const float* w_off  = (const float*)d_in[2];
    const float* b_off  = (const float*)d_in[3];
    const float* w_mask = (const float*)d_in[4];
    const float* b_mask = (const float*)d_in[5];
    float* out = (float*)d_out;

    cudaFuncSetAttribute(deform_kernel,
                         cudaFuncAttributeMaxDynamicSharedMemorySize, DSM_BYTES);

    prep_w_kernel<<<(9*128*128 + 255)/256, 256>>>(w_conv);
    offmask_kernel<<<dim3(16, 16), 128>>>(x, w_off, b_off, w_mask, b_mask);
    deform_kernel<<<dim3(32, 16), 512, DSM_BYTES>>>(x, out);
}

// round 8
// speedup vs baseline: 1.9967x; 1.0516x over previous
#include <cuda_runtime.h>
#include <cuda_fp16.h>
#include <cstdint>

#define BATCH 16
#define CIN   128
#define COUT  128
#define HH    64
#define WW    64

// ---------------------------------------------------------------------------
// Scratch (device globals: allocation-free rule)
// ---------------------------------------------------------------------------
__device__ float g_offmask[(size_t)BATCH*27*HH*WW]; // [b][27][h][w]; 0..17 offsets, 18..26 sigmoid(mask)
// Weights as fp16 (rn), layout [stage s = half*9 + tap][o:128][k:64]
__device__ __half g_wA[18*128*64];

typedef unsigned long long ull;

// ---------------------------------------------------------------------------
// Helpers
// ---------------------------------------------------------------------------
__device__ __forceinline__ uint32_t smem_u32(const void* p){
    uint32_t a;
    asm("{ .reg .u64 t; cvta.to.shared.u64 t, %1; cvt.u32.u64 %0, t; }" : "=r"(a) : "l"(p));
    return a;
}

#define LDMX4(r, addr) \
    asm volatile("ldmatrix.sync.aligned.m8n8.x4.shared.b16 {%0,%1,%2,%3}, [%4];" \
        : "=r"((r)[0]), "=r"((r)[1]), "=r"((r)[2]), "=r"((r)[3]) : "r"(addr))

#define MMA16816(d, a0, a1, a2, a3, b0, b1) \
    asm volatile("mma.sync.aligned.m16n8k16.row.col.f32.f16.f16.f32 " \
        "{%0,%1,%2,%3}, {%4,%5,%6,%7}, {%8,%9}, {%0,%1,%2,%3};" \
        : "+f"((d)[0]), "+f"((d)[1]), "+f"((d)[2]), "+f"((d)[3]) \
        : "r"(a0), "r"(a1), "r"(a2), "r"(a3), "r"(b0), "r"(b1))

#define CP_ASYNC16(dst, src) \
    asm volatile("cp.async.ca.shared.global [%0], [%1], 16;" :: "r"(dst), "l"(src))
#define CP_COMMIT()  asm volatile("cp.async.commit_group;" ::: "memory")
#define CP_WAIT0()   asm volatile("cp.async.wait_group 0;" ::: "memory")

// Named-barrier producer/consumer sync (512 threads total per pair)
#define BAR_SYNC(id)   asm volatile("bar.sync %0, 512;"   :: "r"(id) : "memory")
#define BAR_ARRIVE(id) asm volatile("bar.arrive %0, 512;" :: "r"(id) : "memory")

__device__ __forceinline__ uint32_t pack_h2(float v0, float v1){
    __half h0 = __float2half_rn(v0);
    __half h1 = __float2half_rn(v1);
    return ((uint32_t)__half_as_ushort(h1) << 16) | __half_as_ushort(h0);
}

// FFMA2 helpers for offmask kernel
__device__ __forceinline__ ull pk2(float a, float b){
    ull r; asm("mov.b64 %0, {%1, %2};" : "=l"(r) : "f"(a), "f"(b)); return r;
}
__device__ __forceinline__ ull pk2s(float a){
    ull r; asm("mov.b64 %0, {%1, %1};" : "=l"(r) : "f"(a)); return r;
}
__device__ __forceinline__ ull f2fma(ull a, ull b, ull c){
    ull d; asm("fma.rn.f32x2 %0, %1, %2, %3;" : "=l"(d) : "l"(a), "l"(b), "l"(c)); return d;
}

// ---------------------------------------------------------------------------
// Kernel 1: prep (fp16 weight repack) + fused offset+mask conv (FFMA2 path)
// Grid (16,16), 128 threads. Prep strided across all 256 blocks.
// ---------------------------------------------------------------------------
__global__ __launch_bounds__(128) void offmask_kernel(
    const float* __restrict__ x,     const float* __restrict__ w_conv,
    const float* __restrict__ w_off,  const float* __restrict__ b_off,
    const float* __restrict__ w_mask, const float* __restrict__ b_mask)
{
    __shared__ ull wsm[16*243];

    const int b   = blockIdx.y;
    const int tid = threadIdx.x;

    // ---- prep: w_conv [o][c][n] -> g_wA[s = (c>>6)*9 + n][o][c&63] (fp16 rn)
    {
        const int bid = blockIdx.y * gridDim.x + blockIdx.x;
        for (int i = bid*128 + tid; i < 9*128*128; i += 256*128){
            int n = i / (128*128);
            int o = (i >> 7) & 127;
            int c = i & 127;
            float w = w_conv[((size_t)o*128 + c)*9 + n];
            int s = (c >> 6)*9 + n;
            size_t di = ((size_t)s*128 + o)*64 + (c & 63);
            g_wA[di] = __float2half_rn(w);
        }
    }

    const int r   = tid >> 5;
    const int pg  = tid & 31;
    const int h_  = blockIdx.x*4 + r;
    const int p0  = pg*2;

    ull acc[27];
    #pragma unroll
    for (int i = 0; i < 27; i++) acc[i] = 0ull;

    const float* xb = x + (size_t)b*CIN*HH*WW;

    for (int chunk = 0; chunk < 8; chunk++){
        __syncthreads();
        const int c0 = chunk*16;
        for (int i = tid; i < 16*243; i += 128){
            int cl = i/243, j = i - cl*243;
            int oc = j/9,  k = j - oc*9;
            int c  = c0 + cl;
            float wv = (oc < 18) ? w_off[((size_t)oc*CIN + c)*9 + k]
                                 : w_mask[((size_t)(oc-18)*CIN + c)*9 + k];
            wsm[i] = pk2s(wv);
        }
        __syncthreads();

        for (int cl = 0; cl < 16; cl++){
            const float* xc = xb + (size_t)(c0+cl)*HH*WW;
            ull xp[3][3];
            #pragma unroll
            for (int rr = 0; rr < 3; rr++){
                int y = h_ - 1 + rr;
                bool vy = ((unsigned)y < (unsigned)HH);
                const float* xr = xc + y*WW;
                float v0 = (vy && pg > 0 ) ? xr[p0-1] : 0.f;
                float v1 =  vy             ? xr[p0  ] : 0.f;
                float v2 =  vy             ? xr[p0+1] : 0.f;
                float v3 = (vy && pg < 31) ? xr[p0+2] : 0.f;
                xp[rr][0] = pk2(v0, v1);
                xp[rr][1] = pk2(v1, v2);
                xp[rr][2] = pk2(v2, v3);
            }
            const ull* wc = wsm + cl*243;
            #pragma unroll
            for (int oc = 0; oc < 27; oc++){
                #pragma unroll
                for (int rr = 0; rr < 3; rr++){
                    #pragma unroll
                    for (int kx = 0; kx < 3; kx++){
                        acc[oc] = f2fma(wc[oc*9 + rr*3 + kx], xp[rr][kx], acc[oc]);
                    }
                }
            }
        }
    }

    #pragma unroll
    for (int oc = 0; oc < 27; oc++){
        union { ull u; float2 f; } cv; cv.u = acc[oc];
        float bias = (oc < 18) ? b_off[oc] : b_mask[oc-18];
        float a = cv.f.x + bias;
        float c = cv.f.y + bias;
        if (oc >= 18){
            a = 1.f/(1.f + __expf(-a));
            c = 1.f/(1.f + __expf(-c));
        }
        cv.f.x = a; cv.f.y = c;
        *reinterpret_cast<ull*>(&g_offmask[(((size_t)b*27 + oc)*HH + h_)*WW + p0]) = cv.u;
    }
}

// ---------------------------------------------------------------------------
// Kernel 2: deform gather + mma.sync fp16 single-pass.
// warp-specialized: warps 0-7 produce, warps 8-15 consume. 3-stage ring.
// K-stage order s = half*9 + tap: consecutive stages reuse the same channel
// half (2/3 row overlap) -> L1-resident gather (smem 126KB leaves ~102KB L1).
// Block = (b, 2 h-rows): D[128 o][128 px], K=1152 in 18 stages of 64.
// ---------------------------------------------------------------------------
#define N_STAGE  3
#define OFF_WT   0                       // 4*1152 floats  = 18432 B
#define OFF_AI   18432                   // 4*1152 int16   =  9216 B
#define OFF_STG  27648                   // stages
#define STG_SZ   32768                   // A 16K | B 16K
#define DSM_BYTES (OFF_STG + N_STAGE*STG_SZ)   // 125952

// barrier ids: full[st] = 1+st (1..3), empty[st] = 4+st (4..6)
__device__ __forceinline__ void gather_stage(
    char* bufB, const float* xb,
    const float* s_wt, const short* s_ai, int n_tap, int half, int ptid)
{
    const int p  = ptid & 127;
    const int cg = ptid >> 7;           // 0/1 → 32-channel half of the 64
    const int ci = n_tap*128 + p;
    const float w00 = s_wt[ci],      w01 = s_wt[1152+ci];
    const float w10 = s_wt[2304+ci], w11 = s_wt[3456+ci];
    const int a00 = s_ai[ci],      a01 = s_ai[1152+ci];
    const int a10 = s_ai[2304+ci], a11 = s_ai[3456+ci];
    const float* xp = xb + (size_t)(half*64 + cg*32)*(HH*WW);
    const int prow = p*128;
    const int psw  = p & 7;

    #pragma unroll
    for (int g = 0; g < 4; g++){        // 8 channels -> one 16B chunk
        uint32_t hv[4];
        #pragma unroll
        for (int e = 0; e < 4; e++){
            const float* xc0 = xp + (size_t)(g*8 + e*2)*(HH*WW);
            const float* xc1 = xc0 + HH*WW;
            float v0 = w00*xc0[a00] + w01*xc0[a01] + w10*xc0[a10] + w11*xc0[a11];
            float v1 = w00*xc1[a00] + w01*xc1[a01] + w10*xc1[a10] + w11*xc1[a11];
            hv[e] = pack_h2(v0, v1);
        }
        int chunk = cg*4 + g;
        uint32_t off = prow + (uint32_t)((chunk ^ psw) << 4);
        *(uint4*)(bufB + off) = make_uint4(hv[0], hv[1], hv[2], hv[3]);
    }
}

__device__ __forceinline__ void cpasync_A(uint32_t bufA_u32, int stage_s, int ptid)
{
    const __half* src = g_wA + (size_t)stage_s*128*64;
    #pragma unroll
    for (int r = 0; r < 4; r++){
        int id = r*256 + ptid;          // 0..1023
        int o = id >> 3, q = id & 7;
        uint32_t dst = bufA_u32 + (uint32_t)(o*128 + ((q ^ (o & 7)) << 4));
        CP_ASYNC16(dst, src + (size_t)o*64 + q*8);
    }
}

__device__ __forceinline__ void mma_stage(
    uint32_t sA, uint32_t sB, float acc[2][8][4], int wm, int wn, int lane)
{
    const int ar  = (lane & 7) + (((lane >> 3) & 1) << 3);  // m within 16
    const int akh = (lane >> 4) & 1;
    const int o0  = wm*32 + ar;
    const int o1  = o0 + 16;
    const int br  = (lane & 7) + (((lane >> 4) & 1) << 3);  // n within 16
    const int bkh = (lane >> 3) & 1;

    #pragma unroll
    for (int ks = 0; ks < 4; ks++){
        uint32_t a0[4], a1[4];
        {
            int ca = ks*2 + akh;
            uint32_t off0 = (uint32_t)(o0*128 + ((ca ^ (o0 & 7)) << 4));
            uint32_t off1 = (uint32_t)(o1*128 + ((ca ^ (o1 & 7)) << 4));
            LDMX4(a0, sA + off0);
            LDMX4(a1, sA + off1);
        }
        const int cb = ks*2 + bkh;
        #pragma unroll
        for (int g = 0; g < 4; g++){
            int pr = wn*64 + g*16 + br;
            uint32_t off = (uint32_t)(pr*128 + ((cb ^ (pr & 7)) << 4));
            uint32_t th[4];
            LDMX4(th, sB + off);
            #pragma unroll
            for (int sub = 0; sub < 2; sub++){
                int nf = g*2 + sub;
                MMA16816(acc[0][nf], a0[0],a0[1],a0[2],a0[3], th[2*sub], th[2*sub+1]);
                MMA16816(acc[1][nf], a1[0],a1[1],a1[2],a1[3], th[2*sub], th[2*sub+1]);
            }
        }
    }
}

__global__ __launch_bounds__(512) void deform_kernel(
    const float* __restrict__ x, float* __restrict__ out)
{
    extern __shared__ char dsm[];
    float* s_wt = (float*)(dsm + OFF_WT);
    short* s_ai = (short*)(dsm + OFF_AI);
    const uint32_t u_base = smem_u32(dsm);
    const uint32_t u_stg  = u_base + OFF_STG;

    const int tid  = threadIdx.x;
    const int wid  = tid >> 5;
    const int lane = tid & 31;
    const int h0   = blockIdx.x * 2;
    const int b    = blockIdx.y;

    // ---- corner tables for all (tap n, px) — all 512 threads ----
    const float* om = g_offmask + (size_t)b*27*HH*WW;
    for (int i = tid; i < 1152; i += 512){
        int n = i >> 7, rr = i & 127;
        int hh = rr >> 6, p = rr & 63;
        int h_ = h0 + hh;
        float offy = om[((size_t)(2*n  )*HH + h_)*WW + p];
        float offx = om[((size_t)(2*n+1)*HH + h_)*WW + p];
        float m    = om[((size_t)(18+n )*HH + h_)*WW + p];
        float py = offy + (float)(h_ - 1 + n/3);
        float px = offx + (float)(p  - 1 + n%3);
        float fy = floorf(py), fx = floorf(px);
        int y0 = (int)fy, x0 = (int)fx;
        float ly = py - fy, lx = px - fx;
        float hy = 1.f - ly, hx = 1.f - lx;
        int y1 = y0 + 1, x1 = x0 + 1;
        float vy0 = ((unsigned)y0 < 64u) ? 1.f : 0.f;
        float vy1 = ((unsigned)y1 < 64u) ? 1.f : 0.f;
        float vx0 = ((unsigned)x0 < 64u) ? 1.f : 0.f;
        float vx1 = ((unsigned)x1 < 64u) ? 1.f : 0.f;
        int y0c = min(max(y0,0),63), y1c = min(max(y1,0),63);
        int x0c = min(max(x0,0),63), x1c = min(max(x1,0),63);
        s_wt[0*1152 + i] = m*hy*hx*vy0*vx0;
        s_wt[1*1152 + i] = m*hy*lx*vy0*vx1;
        s_wt[2*1152 + i] = m*ly*hx*vy1*vx0;
        s_wt[3*1152 + i] = m*ly*lx*vy1*vx1;
        s_ai[0*1152 + i] = (short)(y0c*WW + x0c);
        s_ai[1*1152 + i] = (short)(y0c*WW + x1c);
        s_ai[2*1152 + i] = (short)(y1c*WW + x0c);
        s_ai[3*1152 + i] = (short)(y1c*WW + x1c);
    }
    __syncthreads();

    const float* xb = x + (size_t)b*CIN*HH*WW;

    if (wid < 8){
        // ================= PRODUCERS (warps 0-7) =================
        const int ptid = tid;           // 0..255
        for (int s = 0; s < 18; s++){
            const int st = s % N_STAGE;
            if (s >= N_STAGE) BAR_SYNC(4 + st);            // wait empty
            const uint32_t uc = u_stg + (uint32_t)st*STG_SZ;
            cpasync_A(uc, s, ptid);
            CP_COMMIT();
            // s = half*9 + tap
            const int half = (s >= 9);
            const int ntap = s - half*9;
            gather_stage(dsm + OFF_STG + st*STG_SZ + 16384, xb, s_wt, s_ai,
                         ntap, half, ptid);
            CP_WAIT0();
            BAR_ARRIVE(1 + st);                            // signal full
        }
    } else {
        // ================= CONSUMERS (warps 8-15) =================
        const int cwid = wid - 8;
        const int wm   = cwid & 3;
        const int wn   = cwid >> 2;

        float acc[2][8][4];
        #pragma unroll
        for (int a = 0; a < 2; a++)
            #pragma unroll
            for (int f = 0; f < 8; f++)
                #pragma unroll
                for (int e = 0; e < 4; e++) acc[a][f][e] = 0.f;

        for (int s = 0; s < 18; s++){
            const int st = s % N_STAGE;
            BAR_SYNC(1 + st);                              // wait full
            const uint32_t uc = u_stg + (uint32_t)st*STG_SZ;
            mma_stage(uc, uc + 16384, acc, wm, wn, lane);
            if (s < 18 - N_STAGE) BAR_ARRIVE(4 + st);      // signal empty
        }

        // ---- epilogue: D[o][px] -> out[b][o][h0+wn][w] ----
        const int h_ = h0 + wn;
        #pragma unroll
        for (int mf = 0; mf < 2; mf++){
            int o = wm*32 + mf*16 + (lane >> 2);
            float* p0 = out + (((size_t)b*COUT + o    )*HH + h_)*WW;
            float* p1 = out + (((size_t)b*COUT + o + 8)*HH + h_)*WW;
            #pragma unroll
            for (int nf = 0; nf < 8; nf++){
                int w = nf*8 + 2*(lane & 3);
                *(float2*)(p0 + w) = make_float2(acc[mf][nf][0], acc[mf][nf][1]);
                *(float2*)(p1 + w) = make_float2(acc[mf][nf][2], acc[mf][nf][3]);
            }
        }
    }
}

// ---------------------------------------------------------------------------
extern "C" void kernel_launch(void* const* d_in, const int* in_sizes, int n_in,
                              void* d_out, int out_size)
{
    const float* x      = (const float*)d_in[0];
    const float* w_conv = (const float*)d_in[1];
    const float* w_off  = (const float*)d_in[2];
    const float* b_off  = (const float*)d_in[3];
    const float* w_mask = (const float*)d_in[4];
    const float* b_mask = (const float*)d_in[5];
    float* out = (float*)d_out;

    cudaFuncSetAttribute(deform_kernel,
                         cudaFuncAttributeMaxDynamicSharedMemorySize, DSM_BYTES);

    offmask_kernel<<<dim3(16, 16), 128>>>(x, w_conv, w_off, b_off, w_mask, b_mask);
    deform_kernel<<<dim3(32, 16), 512, DSM_BYTES>>>(x, out);
}

// round 9
// speedup vs baseline: 3.4616x; 1.7336x over previous
#include <cuda_runtime.h>
#include <cuda_fp16.h>
#include <cstdint>

#define BATCH 16
#define CIN   128
#define COUT  128
#define HH    64
#define WW    64

// ---------------------------------------------------------------------------
// Scratch (device globals: allocation-free rule)
// ---------------------------------------------------------------------------
__device__ float g_offmask[(size_t)BATCH*27*HH*WW]; // [b][27][h][w]; 0..17 offsets, 18..26 sigmoid(mask)
// Main-conv weights fp16, layout [stage s = half*9 + tap][o:128][k:64]
__device__ __half g_wA[18*128*64];
// Offset/mask-conv weights fp16, layout [stage][o:32 (27 used)][k:64]
__device__ __half g_wOM[18*32*64];

typedef unsigned long long ull;

// ---------------------------------------------------------------------------
// Helpers
// ---------------------------------------------------------------------------
__device__ __forceinline__ uint32_t smem_u32(const void* p){
    uint32_t a;
    asm("{ .reg .u64 t; cvta.to.shared.u64 t, %1; cvt.u32.u64 %0, t; }" : "=r"(a) : "l"(p));
    return a;
}

#define LDMX4(r, addr) \
    asm volatile("ldmatrix.sync.aligned.m8n8.x4.shared.b16 {%0,%1,%2,%3}, [%4];" \
        : "=r"((r)[0]), "=r"((r)[1]), "=r"((r)[2]), "=r"((r)[3]) : "r"(addr))

#define MMA16816(d, a0, a1, a2, a3, b0, b1) \
    asm volatile("mma.sync.aligned.m16n8k16.row.col.f32.f16.f16.f32 " \
        "{%0,%1,%2,%3}, {%4,%5,%6,%7}, {%8,%9}, {%0,%1,%2,%3};" \
        : "+f"((d)[0]), "+f"((d)[1]), "+f"((d)[2]), "+f"((d)[3]) \
        : "r"(a0), "r"(a1), "r"(a2), "r"(a3), "r"(b0), "r"(b1))

#define CP_ASYNC16(dst, src) \
    asm volatile("cp.async.ca.shared.global [%0], [%1], 16;" :: "r"(dst), "l"(src))
#define CP_COMMIT()  asm volatile("cp.async.commit_group;" ::: "memory")
#define CP_WAIT0()   asm volatile("cp.async.wait_group 0;" ::: "memory")

// Named-barrier producer/consumer sync (512 threads total per pair)
#define BAR_SYNC(id)   asm volatile("bar.sync %0, 512;"   :: "r"(id) : "memory")
#define BAR_ARRIVE(id) asm volatile("bar.arrive %0, 512;" :: "r"(id) : "memory")

__device__ __forceinline__ uint32_t pack_h2(float v0, float v1){
    __half h0 = __float2half_rn(v0);
    __half h1 = __float2half_rn(v1);
    return ((uint32_t)__half_as_ushort(h1) << 16) | __half_as_ushort(h0);
}

// ---------------------------------------------------------------------------
// Kernel 0: prep fp16 weight tiles for both GEMMs
// ---------------------------------------------------------------------------
__global__ void prep_w_kernel(const float* __restrict__ w_conv,
                              const float* __restrict__ w_off,
                              const float* __restrict__ w_mask){
    int i = blockIdx.x * blockDim.x + threadIdx.x;
    if (i < 18*128*64){
        // g_wA: w_conv [o][c][n] -> [s=(c>>6)*9+n][o][c&63]
        int n = i / (128*128);
        int o = (i >> 7) & 127;
        int c = i & 127;
        float w = w_conv[((size_t)o*128 + c)*9 + n];
        int s = (c >> 6)*9 + n;
        size_t di = ((size_t)s*128 + o)*64 + (c & 63);
        g_wA[di] = __float2half_rn(w);
    }
    if (i < 18*32*64){
        // g_wOM: [s][o:32][cl], o<18 offsets, 18..26 mask, 27..31 zero
        int s  = i >> 11;            // /2048
        int o  = (i >> 6) & 31;
        int cl = i & 63;
        int half = s / 9, n = s - half*9;
        int c = half*64 + cl;
        float w = 0.f;
        if (o < 18)      w = w_off [((size_t)o*128 + c)*9 + n];
        else if (o < 27) w = w_mask[((size_t)(o-18)*128 + c)*9 + n];
        g_wOM[i] = __float2half_rn(w);
    }
}

// ---------------------------------------------------------------------------
// Kernel 1: offset+mask conv as fp16 MMA, warp-specialized.
// Block = (b, 2 h-rows): D[32 oc][128 px], K=1152 in 18 half-major stages.
// Producers (w0-7): B = shifted x window (zero-pad). Consumers (w8-15): MMA.
// ---------------------------------------------------------------------------
#define OM_NSTG   3
#define OM_STG_SZ 20480            // A 4K | B 16K
#define OM_DSM    (OM_NSTG*OM_STG_SZ)   // 61440

__global__ __launch_bounds__(512) void offmask_mma_kernel(
    const float* __restrict__ x,
    const float* __restrict__ b_off, const float* __restrict__ b_mask)
{
    extern __shared__ char dsm[];
    const uint32_t u_stg = smem_u32(dsm);

    const int tid  = threadIdx.x;
    const int wid  = tid >> 5;
    const int lane = tid & 31;
    const int h0   = blockIdx.x * 2;
    const int b    = blockIdx.y;
    const float* xb = x + (size_t)b*CIN*HH*WW;

    if (wid < 8){
        // ---------------- PRODUCERS ----------------
        const int p  = tid & 127;
        const int cg = tid >> 7;            // 0/1: 32-ch half of the 64
        const int hh = p >> 6, wp = p & 63;
        const int prow = p*128;
        const int psw  = p & 7;

        for (int s = 0; s < 18; s++){
            const int st = s % OM_NSTG;
            if (s >= OM_NSTG) BAR_SYNC(4 + st);          // wait empty
            const uint32_t uc = u_stg + (uint32_t)st*OM_STG_SZ;

            // A tile: 32 o x 64 c fp16 = 256 chunks of 16B, 1 per thread
            {
                const __half* src = g_wOM + (size_t)s*32*64;
                int id = tid;                // 0..255
                int o = id >> 3, q = id & 7;
                uint32_t dst = uc + (uint32_t)(o*128 + ((q ^ (o & 7)) << 4));
                CP_ASYNC16(dst, src + (size_t)o*64 + q*8);
                CP_COMMIT();
            }

            // B tile: shifted window of x, zero-padded
            {
                const int half = (s >= 9);
                const int ntap = s - half*9;
                const int ky = ntap / 3, kx = ntap - ky*3;
                const int y  = h0 + hh - 1 + ky;
                const int xc = wp - 1 + kx;
                const bool valid = ((unsigned)y < 64u) & ((unsigned)xc < 64u);
                const float* src = xb + ((size_t)(half*64 + cg*32))*(HH*WW) + y*WW + xc;
                char* bufB = dsm + st*OM_STG_SZ + 4096;
                #pragma unroll
                for (int g = 0; g < 4; g++){
                    uint32_t hv[4];
                    #pragma unroll
                    for (int e = 0; e < 4; e++){
                        int c0 = g*8 + e*2;
                        float v0 = valid ? src[(size_t)c0*(HH*WW)]     : 0.f;
                        float v1 = valid ? src[(size_t)(c0+1)*(HH*WW)] : 0.f;
                        hv[e] = pack_h2(v0, v1);
                    }
                    uint32_t off = prow + (uint32_t)(((cg*4 + g) ^ psw) << 4);
                    *(uint4*)(bufB + off) = make_uint4(hv[0], hv[1], hv[2], hv[3]);
                }
            }
            CP_WAIT0();
            BAR_ARRIVE(1 + st);                          // signal full
        }
    } else {
        // ---------------- CONSUMERS ----------------
        const int wn = wid - 8;              // n-block of 16 px
        const int ar  = (lane & 7) + (((lane >> 3) & 1) << 3);
        const int akh = (lane >> 4) & 1;
        const int br  = (lane & 7) + (((lane >> 4) & 1) << 3);
        const int bkh = (lane >> 3) & 1;

        float acc[2][2][4];
        #pragma unroll
        for (int a = 0; a < 2; a++)
            #pragma unroll
            for (int f = 0; f < 2; f++)
                #pragma unroll
                for (int e = 0; e < 4; e++) acc[a][f][e] = 0.f;

        for (int s = 0; s < 18; s++){
            const int st = s % OM_NSTG;
            BAR_SYNC(1 + st);                            // wait full
            const uint32_t sA = u_stg + (uint32_t)st*OM_STG_SZ;
            const uint32_t sB = sA + 4096;
            #pragma unroll
            for (int ks = 0; ks < 4; ks++){
                uint32_t a0[4], a1[4];
                {
                    int ca = ks*2 + akh;
                    int o0 = ar, o1 = ar + 16;
                    LDMX4(a0, sA + (uint32_t)(o0*128 + ((ca ^ (o0 & 7)) << 4)));
                    LDMX4(a1, sA + (uint32_t)(o1*128 + ((ca ^ (o1 & 7)) << 4)));
                }
                const int cb = ks*2 + bkh;
                const int pr = wn*16 + br;
                uint32_t th[4];
                LDMX4(th, sB + (uint32_t)(pr*128 + ((cb ^ (pr & 7)) << 4)));
                #pragma unroll
                for (int sub = 0; sub < 2; sub++){
                    MMA16816(acc[0][sub], a0[0],a0[1],a0[2],a0[3], th[2*sub], th[2*sub+1]);
                    MMA16816(acc[1][sub], a1[0],a1[1],a1[2],a1[3], th[2*sub], th[2*sub+1]);
                }
            }
            if (s < 18 - OM_NSTG) BAR_ARRIVE(4 + st);    // signal empty
        }

        // ---- epilogue: bias, sigmoid(mask), write g_offmask ----
        #pragma unroll
        for (int mf = 0; mf < 2; mf++){
            #pragma unroll
            for (int sub = 0; sub < 2; sub++){
                #pragma unroll
                for (int e = 0; e < 4; e++){
                    int o  = mf*16 + (lane >> 2) + ((e >> 1) << 3);
                    int px = wn*16 + sub*8 + 2*(lane & 3) + (e & 1);
                    if (o < 27){
                        float v = acc[mf][sub][e];
                        if (o < 18) v += b_off[o];
                        else        v = 1.f/(1.f + __expf(-(v + b_mask[o-18])));
                        int hh = px >> 6, w = px & 63;
                        g_offmask[(((size_t)b*27 + o)*HH + h0 + hh)*WW + w] = v;
                    }
                }
            }
        }
    }
}

// ---------------------------------------------------------------------------
// Kernel 2: deform gather + mma.sync fp16 single-pass (unchanged from R8).
// warp-specialized, 3-stage ring, half-major K-stage order for L1 reuse.
// Block = (b, 2 h-rows): D[128 o][128 px], K=1152 in 18 stages of 64.
// ---------------------------------------------------------------------------
#define N_STAGE  3
#define OFF_WT   0                       // 4*1152 floats  = 18432 B
#define OFF_AI   18432                   // 4*1152 int16   =  9216 B
#define OFF_STG  27648                   // stages
#define STG_SZ   32768                   // A 16K | B 16K
#define DSM_BYTES (OFF_STG + N_STAGE*STG_SZ)   // 125952

__device__ __forceinline__ void gather_stage(
    char* bufB, const float* xb,
    const float* s_wt, const short* s_ai, int n_tap, int half, int ptid)
{
    const int p  = ptid & 127;
    const int cg = ptid >> 7;
    const int ci = n_tap*128 + p;
    const float w00 = s_wt[ci],      w01 = s_wt[1152+ci];
    const float w10 = s_wt[2304+ci], w11 = s_wt[3456+ci];
    const int a00 = s_ai[ci],      a01 = s_ai[1152+ci];
    const int a10 = s_ai[2304+ci], a11 = s_ai[3456+ci];
    const float* xp = xb + (size_t)(half*64 + cg*32)*(HH*WW);
    const int prow = p*128;
    const int psw  = p & 7;

    #pragma unroll
    for (int g = 0; g < 4; g++){
        uint32_t hv[4];
        #pragma unroll
        for (int e = 0; e < 4; e++){
            const float* xc0 = xp + (size_t)(g*8 + e*2)*(HH*WW);
            const float* xc1 = xc0 + HH*WW;
            float v0 = w00*xc0[a00] + w01*xc0[a01] + w10*xc0[a10] + w11*xc0[a11];
            float v1 = w00*xc1[a00] + w01*xc1[a01] + w10*xc1[a10] + w11*xc1[a11];
            hv[e] = pack_h2(v0, v1);
        }
        int chunk = cg*4 + g;
        uint32_t off = prow + (uint32_t)((chunk ^ psw) << 4);
        *(uint4*)(bufB + off) = make_uint4(hv[0], hv[1], hv[2], hv[3]);
    }
}

__device__ __forceinline__ void cpasync_A(uint32_t bufA_u32, int stage_s, int ptid)
{
    const __half* src = g_wA + (size_t)stage_s*128*64;
    #pragma unroll
    for (int r = 0; r < 4; r++){
        int id = r*256 + ptid;
        int o = id >> 3, q = id & 7;
        uint32_t dst = bufA_u32 + (uint32_t)(o*128 + ((q ^ (o & 7)) << 4));
        CP_ASYNC16(dst, src + (size_t)o*64 + q*8);
    }
}

__device__ __forceinline__ void mma_stage(
    uint32_t sA, uint32_t sB, float acc[2][8][4], int wm, int wn, int lane)
{
    const int ar  = (lane & 7) + (((lane >> 3) & 1) << 3);
    const int akh = (lane >> 4) & 1;
    const int o0  = wm*32 + ar;
    const int o1  = o0 + 16;
    const int br  = (lane & 7) + (((lane >> 4) & 1) << 3);
    const int bkh = (lane >> 3) & 1;

    #pragma unroll
    for (int ks = 0; ks < 4; ks++){
        uint32_t a0[4], a1[4];
        {
            int ca = ks*2 + akh;
            LDMX4(a0, sA + (uint32_t)(o0*128 + ((ca ^ (o0 & 7)) << 4)));
            LDMX4(a1, sA + (uint32_t)(o1*128 + ((ca ^ (o1 & 7)) << 4)));
        }
        const int cb = ks*2 + bkh;
        #pragma unroll
        for (int g = 0; g < 4; g++){
            int pr = wn*64 + g*16 + br;
            uint32_t th[4];
            LDMX4(th, sB + (uint32_t)(pr*128 + ((cb ^ (pr & 7)) << 4)));
            #pragma unroll
            for (int sub = 0; sub < 2; sub++){
                int nf = g*2 + sub;
                MMA16816(acc[0][nf], a0[0],a0[1],a0[2],a0[3], th[2*sub], th[2*sub+1]);
                MMA16816(acc[1][nf], a1[0],a1[1],a1[2],a1[3], th[2*sub], th[2*sub+1]);
            }
        }
    }
}

__global__ __launch_bounds__(512) void deform_kernel(
    const float* __restrict__ x, float* __restrict__ out)
{
    extern __shared__ char dsm[];
    float* s_wt = (float*)(dsm + OFF_WT);
    short* s_ai = (short*)(dsm + OFF_AI);
    const uint32_t u_base = smem_u32(dsm);
    const uint32_t u_stg  = u_base + OFF_STG;

    const int tid  = threadIdx.x;
    const int wid  = tid >> 5;
    const int lane = tid & 31;
    const int h0   = blockIdx.x * 2;
    const int b    = blockIdx.y;

    const float* om = g_offmask + (size_t)b*27*HH*WW;
    for (int i = tid; i < 1152; i += 512){
        int n = i >> 7, rr = i & 127;
        int hh = rr >> 6, p = rr & 63;
        int h_ = h0 + hh;
        float offy = om[((size_t)(2*n  )*HH + h_)*WW + p];
        float offx = om[((size_t)(2*n+1)*HH + h_)*WW + p];
        float m    = om[((size_t)(18+n )*HH + h_)*WW + p];
        float py = offy + (float)(h_ - 1 + n/3);
        float px = offx + (float)(p  - 1 + n%3);
        float fy = floorf(py), fx = floorf(px);
        int y0 = (int)fy, x0 = (int)fx;
        float ly = py - fy, lx = px - fx;
        float hy = 1.f - ly, hx = 1.f - lx;
        int y1 = y0 + 1, x1 = x0 + 1;
        float vy0 = ((unsigned)y0 < 64u) ? 1.f : 0.f;
        float vy1 = ((unsigned)y1 < 64u) ? 1.f : 0.f;
        float vx0 = ((unsigned)x0 < 64u) ? 1.f : 0.f;
        float vx1 = ((unsigned)x1 < 64u) ? 1.f : 0.f;
        int y0c = min(max(y0,0),63), y1c = min(max(y1,0),63);
        int x0c = min(max(x0,0),63), x1c = min(max(x1,0),63);
        s_wt[0*1152 + i] = m*hy*hx*vy0*vx0;
        s_wt[1*1152 + i] = m*hy*lx*vy0*vx1;
        s_wt[2*1152 + i] = m*ly*hx*vy1*vx0;
        s_wt[3*1152 + i] = m*ly*lx*vy1*vx1;
        s_ai[0*1152 + i] = (short)(y0c*WW + x0c);
        s_ai[1*1152 + i] = (short)(y0c*WW + x1c);
        s_ai[2*1152 + i] = (short)(y1c*WW + x0c);
        s_ai[3*1152 + i] = (short)(y1c*WW + x1c);
    }
    __syncthreads();

    const float* xb = x + (size_t)b*CIN*HH*WW;

    if (wid < 8){
        const int ptid = tid;
        for (int s = 0; s < 18; s++){
            const int st = s % N_STAGE;
            if (s >= N_STAGE) BAR_SYNC(4 + st);
            const uint32_t uc = u_stg + (uint32_t)st*STG_SZ;
            cpasync_A(uc, s, ptid);
            CP_COMMIT();
            const int half = (s >= 9);
            const int ntap = s - half*9;
            gather_stage(dsm + OFF_STG + st*STG_SZ + 16384, xb, s_wt, s_ai,
                         ntap, half, ptid);
            CP_WAIT0();
            BAR_ARRIVE(1 + st);
        }
    } else {
        const int cwid = wid - 8;
        const int wm   = cwid & 3;
        const int wn   = cwid >> 2;

        float acc[2][8][4];
        #pragma unroll
        for (int a = 0; a < 2; a++)
            #pragma unroll
            for (int f = 0; f < 8; f++)
                #pragma unroll
                for (int e = 0; e < 4; e++) acc[a][f][e] = 0.f;

        for (int s = 0; s < 18; s++){
            const int st = s % N_STAGE;
            BAR_SYNC(1 + st);
            const uint32_t uc = u_stg + (uint32_t)st*STG_SZ;
            mma_stage(uc, uc + 16384, acc, wm, wn, lane);
            if (s < 18 - N_STAGE) BAR_ARRIVE(4 + st);
        }

        const int h_ = h0 + wn;
        #pragma unroll
        for (int mf = 0; mf < 2; mf++){
            int o = wm*32 + mf*16 + (lane >> 2);
            float* p0 = out + (((size_t)b*COUT + o    )*HH + h_)*WW;
            float* p1 = out + (((size_t)b*COUT + o + 8)*HH + h_)*WW;
            #pragma unroll
            for (int nf = 0; nf < 8; nf++){
                int w = nf*8 + 2*(lane & 3);
                *(float2*)(p0 + w) = make_float2(acc[mf][nf][0], acc[mf][nf][1]);
                *(float2*)(p1 + w) = make_float2(acc[mf][nf][2], acc[mf][nf][3]);
            }
        }
    }
}

// ---------------------------------------------------------------------------
extern "C" void kernel_launch(void* const* d_in, const int* in_sizes, int n_in,
                              void* d_out, int out_size)
{
    const float* x      = (const float*)d_in[0];
    const float* w_conv = (const float*)d_in[1];
    const float* w_off  = (const float*)d_in[2];
    const float* b_off  = (const float*)d_in[3];
    const float* w_mask = (const float*)d_in[4];
    const float* b_mask = (const float*)d_in[5];
    float* out = (float*)d_out;

    cudaFuncSetAttribute(offmask_mma_kernel,
                         cudaFuncAttributeMaxDynamicSharedMemorySize, OM_DSM);
    cudaFuncSetAttribute(deform_kernel,
                         cudaFuncAttributeMaxDynamicSharedMemorySize, DSM_BYTES);

    prep_w_kernel<<<(18*128*64 + 255)/256, 256>>>(w_conv, w_off, w_mask);
    offmask_mma_kernel<<<dim3(32, 16), 512, OM_DSM>>>(x, b_off, b_mask);
    deform_kernel<<<dim3(32, 16), 512, DSM_BYTES>>>(x, out);
}